// round 1
// baseline (speedup 1.0000x reference)
#include <cuda_runtime.h>
#include <math.h>

// ---------------- problem constants ----------------
#define BB 4
#define CIN 512
#define MIDC 512
#define HH 50
#define WW 50
#define PIX 2500
#define KTOT 4608          // 512*9
#define AA 9
#define NANCH 22500        // 2500*9
#define NPRE 1200
#define NPOST 300
#define IMGSZ 800.0f
#define NMS_THRESH 0.7f
#define MINSZ 16.0f

#define LOCS_OFF   0
#define SCORES_OFF 360000  // 4*22500*4
#define ROIS_OFF   540000  // + 4*22500*2
// total out = 544800

// ---------------- scratch (static device globals; no alloc allowed) ----------------
__device__ float g_h[BB * MIDC * PIX];        // conv1 output (relu), [b][c][p]
__device__ float g_s[BB * NANCH];             // filtered fg scores
__device__ float g_boxes[BB * NANCH * 4];     // clipped candidate boxes

// ================= Kernel 1: 3x3 conv + bias + relu as implicit GEMM =================
// C[oc, p] = sum_k W1[oc, k] * im2col(X)[k, p],  k = c*9 + ky*3 + kx (contiguous in W1)
// Tiles: BM=128 (oc), BN=128 (pixels), BK=16. 256 threads, 8x8 register tile.
__global__ __launch_bounds__(256) void conv3x3_relu(const float* __restrict__ X,
                                                    const float* __restrict__ W1,
                                                    const float* __restrict__ b1) {
    __shared__ float As[16][128];   // As[k][m]
    __shared__ float Bs[16][128];   // Bs[k][n]

    const int b = blockIdx.z;
    const int mBase = blockIdx.y * 128;
    const int nBase = blockIdx.x * 128;
    const int tid = threadIdx.x;
    const int ty = tid >> 4;        // 0..15
    const int tx = tid & 15;        // 0..15

    float acc[8][8];
#pragma unroll
    for (int i = 0; i < 8; i++)
#pragma unroll
        for (int j = 0; j < 8; j++) acc[i][j] = 0.f;

    // B-load mapping: 128 consecutive threads cover n (coalesced), 2 k-rows per pass
    const int nb  = tid & 127;
    const int kb0 = tid >> 7;       // 0 or 1
    const int n_g = nBase + nb;
    const int y0  = n_g / 50;
    const int x0  = n_g - y0 * 50;
    const bool nvalid = (n_g < PIX);
    const float* Xb = X + (size_t)b * CIN * PIX;

    for (int k0 = 0; k0 < KTOT; k0 += 16) {
        // --- load A tile (weights): 128x16, float4 along k ---
        {
            int m  = tid >> 2;            // 0..63
            int kq = (tid & 3) << 2;      // 0,4,8,12
#pragma unroll
            for (int mm = 0; mm < 2; mm++) {
                int mr = m + mm * 64;
                float4 v = *reinterpret_cast<const float4*>(
                    &W1[(size_t)(mBase + mr) * KTOT + k0 + kq]);
                As[kq + 0][mr] = v.x;
                As[kq + 1][mr] = v.y;
                As[kq + 2][mr] = v.z;
                As[kq + 3][mr] = v.w;
            }
        }
        // --- load B tile (implicit im2col): 16x128 ---
#pragma unroll
        for (int j = 0; j < 8; j++) {
            int k  = kb0 + (j << 1);
            int kg = k0 + k;
            int c  = kg / 9;
            int r  = kg - c * 9;
            int ry = r / 3;
            int rx = r - ry * 3;
            int yy = y0 + ry - 1;
            int xx = x0 + rx - 1;
            float v = 0.f;
            if (nvalid && (unsigned)yy < 50u && (unsigned)xx < 50u)
                v = __ldg(&Xb[c * PIX + yy * 50 + xx]);
            Bs[k][nb] = v;
        }
        __syncthreads();

#pragma unroll
        for (int kk = 0; kk < 16; kk++) {
            float4 a0 = *reinterpret_cast<float4*>(&As[kk][ty * 8]);
            float4 a1 = *reinterpret_cast<float4*>(&As[kk][ty * 8 + 4]);
            float4 c0 = *reinterpret_cast<float4*>(&Bs[kk][tx * 8]);
            float4 c1 = *reinterpret_cast<float4*>(&Bs[kk][tx * 8 + 4]);
            float av[8] = {a0.x, a0.y, a0.z, a0.w, a1.x, a1.y, a1.z, a1.w};
            float bv[8] = {c0.x, c0.y, c0.z, c0.w, c1.x, c1.y, c1.z, c1.w};
#pragma unroll
            for (int i = 0; i < 8; i++)
#pragma unroll
                for (int j = 0; j < 8; j++) acc[i][j] = fmaf(av[i], bv[j], acc[i][j]);
        }
        __syncthreads();
    }

    // --- epilogue: +bias, relu, store to g_h ---
#pragma unroll
    for (int i = 0; i < 8; i++) {
        int m = mBase + ty * 8 + i;
        float bias = b1[m];
#pragma unroll
        for (int jj = 0; jj < 8; jj += 4) {
            int n = nBase + tx * 8 + jj;
            if (n < PIX) {  // n is multiple of 4, PIX multiple of 4 -> safe float4
                float4 v;
                v.x = fmaxf(acc[i][jj + 0] + bias, 0.f);
                v.y = fmaxf(acc[i][jj + 1] + bias, 0.f);
                v.z = fmaxf(acc[i][jj + 2] + bias, 0.f);
                v.w = fmaxf(acc[i][jj + 3] + bias, 0.f);
                *reinterpret_cast<float4*>(&g_h[(size_t)(b * MIDC + m) * PIX + n]) = v;
            }
        }
    }
}

// ================= Kernel 2: 1x1 heads -> rpn_locs / rpn_scores in d_out =================
__global__ void heads_kernel(const float* __restrict__ Wl, const float* __restrict__ bl,
                             const float* __restrict__ Ws, const float* __restrict__ bs,
                             float* __restrict__ out) {
    int idx = blockIdx.x * blockDim.x + threadIdx.x;
    const int TOT = BB * 54 * PIX;
    if (idx >= TOT) return;
    int p  = idx % PIX;
    int t  = idx / PIX;
    int oc = t % 54;
    int b  = t / 54;

    const float* hp = g_h + (size_t)(b * MIDC) * PIX + p;
    const float* w;
    float bias;
    if (oc < 36) { w = Wl + oc * MIDC;        bias = bl[oc]; }
    else         { w = Ws + (oc - 36) * MIDC; bias = bs[oc - 36]; }

    float acc = 0.f;
#pragma unroll 8
    for (int c = 0; c < MIDC; c++)
        acc = fmaf(__ldg(hp + c * PIX), __ldg(w + c), acc);
    acc += bias;

    if (oc < 36) {
        int a = oc >> 2, d = oc & 3;
        out[LOCS_OFF + ((size_t)b * NANCH + p * AA + a) * 4 + d] = acc;
    } else {
        int o = oc - 36;
        int a = o >> 1, cc = o & 1;
        out[SCORES_OFF + ((size_t)b * NANCH + p * AA + a) * 2 + cc] = acc;
    }
}

// ================= Kernel 3: per-anchor prep (fg softmax, loc2bbox, clip, min-size) ===========
__global__ void prep_kernel(const float* __restrict__ out) {
    int idx = blockIdx.x * blockDim.x + threadIdx.x;
    if (idx >= BB * NANCH) return;
    int i = idx % NANCH;

    // fg = softmax([s0,s1])[1], numerically like jax (subtract max)
    float s0 = out[SCORES_OFF + (size_t)idx * 2 + 0];
    float s1 = out[SCORES_OFF + (size_t)idx * 2 + 1];
    float m  = fmaxf(s0, s1);
    float e0 = expf(s0 - m), e1 = expf(s1 - m);
    float fg = e1 / (e0 + e1);

    // anchor (match numpy: double math, cast to float like the reference table)
    int p  = i / AA, a = i - (i / AA) * AA;
    int iy = p / 50, ix = p - iy * 50;
    const double ratios[3] = {0.5, 1.0, 2.0};
    const double scales[3] = {8.0, 16.0, 32.0};
    int ri = a / 3;
    double r  = ratios[ri];
    double sc = scales[a - ri * 3];
    double hhd = 16.0 * sc * sqrt(r);
    double wwd = 16.0 * sc * sqrt(1.0 / r);
    float y1b = (float)(8.0 - hhd * 0.5);
    float x1b = (float)(8.0 - wwd * 0.5);
    float y2b = (float)(8.0 + hhd * 0.5);
    float x2b = (float)(8.0 + wwd * 0.5);
    float sy = (float)(iy * 16), sx = (float)(ix * 16);
    float ay1 = sy + y1b, ax1 = sx + x1b, ay2 = sy + y2b, ax2 = sx + x2b;

    float ha = ay2 - ay1, wa = ax2 - ax1;
    float cy = ay1 + 0.5f * ha, cx = ax1 + 0.5f * wa;

    const float* lp = out + LOCS_OFF + (size_t)idx * 4;
    float dy = lp[0], dx = lp[1], dh = lp[2], dw = lp[3];
    float ncy = dy * ha + cy;
    float ncx = dx * wa + cx;
    float nh = expf(dh) * ha;
    float nw = expf(dw) * wa;

    float y1 = fminf(fmaxf(ncy - 0.5f * nh, 0.f), IMGSZ);
    float x1 = fminf(fmaxf(ncx - 0.5f * nw, 0.f), IMGSZ);
    float y2 = fminf(fmaxf(ncy + 0.5f * nh, 0.f), IMGSZ);
    float x2 = fminf(fmaxf(ncx + 0.5f * nw, 0.f), IMGSZ);

    *reinterpret_cast<float4*>(&g_boxes[(size_t)idx * 4]) = make_float4(y1, x1, y2, x2);
    float hs = y2 - y1, ws2 = x2 - x1;
    g_s[idx] = (hs >= MINSZ && ws2 >= MINSZ) ? fg : -INFINITY;
}

// ================= Kernel 4: per-batch propose (radix-select + sort + NMS + emit) =============
__device__ __forceinline__ unsigned long long make_key(float s, int i) {
    unsigned int u = __float_as_uint(s);
    u = (u & 0x80000000u) ? ~u : (u | 0x80000000u);  // monotone: larger float -> larger u
    unsigned int inv = ~u;                            // ascending inv == descending score
    return (((unsigned long long)inv) << 32) | (unsigned int)i;  // tie-break: low index first
}

__global__ __launch_bounds__(1024) void propose_kernel(float* __restrict__ out) {
    const int b = blockIdx.x;
    const int tid = threadIdx.x;

    __shared__ unsigned int hist[2048];
    __shared__ unsigned long long keys[2048];
    __shared__ float4 sboxes[NPRE];
    __shared__ unsigned char sup[NPRE];
    __shared__ unsigned long long sh_prefix;
    __shared__ int sh_rem;
    __shared__ int sh_cnt;

    const float* sb = g_s + (size_t)b * NANCH;

    // --- radix select: find the key of rank NPRE-1 (ascending, keys unique) ---
    unsigned long long prefix = 0ull;
    int pb = 0;
    int remaining = NPRE - 1;
    const int widths[6] = {11, 11, 11, 11, 11, 9};
    for (int pass = 0; pass < 6; pass++) {
        int w  = widths[pass];
        int nb = 1 << w;
        for (int t = tid; t < 2048; t += 1024) hist[t] = 0;
        __syncthreads();
        int shift = 64 - pb - w;
        for (int i = tid; i < NANCH; i += 1024) {
            unsigned long long key = make_key(sb[i], i);
            bool match = (pb == 0) || ((key >> (64 - pb)) == prefix);
            if (match) {
                unsigned int d = (unsigned int)((key >> shift) & (unsigned long long)(nb - 1));
                atomicAdd(&hist[d], 1u);
            }
        }
        __syncthreads();
        if (tid == 0) {
            unsigned int cum = 0;
            for (int d = 0; d < nb; d++) {
                unsigned int c = hist[d];
                if (cum + c > (unsigned int)remaining) {
                    sh_prefix = (prefix << w) | (unsigned long long)d;
                    sh_rem = remaining - (int)cum;
                    break;
                }
                cum += c;
            }
        }
        __syncthreads();
        prefix = sh_prefix;
        remaining = sh_rem;
        pb += w;
        __syncthreads();
    }
    const unsigned long long pivot = prefix;

    // --- compact the NPRE smallest keys ---
    if (tid == 0) sh_cnt = 0;
    __syncthreads();
    for (int i = tid; i < NANCH; i += 1024) {
        unsigned long long key = make_key(sb[i], i);
        if (key <= pivot) {
            int pos = atomicAdd(&sh_cnt, 1);
            if (pos < 2048) keys[pos] = key;
        }
    }
    __syncthreads();
    int cnt = sh_cnt;
    if (cnt > 2048) cnt = 2048;
    for (int t = tid; t < 2048; t += 1024)
        if (t >= cnt) keys[t] = 0xFFFFFFFFFFFFFFFFull;
    __syncthreads();

    // --- bitonic sort ascending (2048 elems) -> order = score desc, index asc ---
    for (int k = 2; k <= 2048; k <<= 1) {
        for (int j = k >> 1; j > 0; j >>= 1) {
            for (int t = tid; t < 2048; t += 1024) {
                int ixj = t ^ j;
                if (ixj > t) {
                    unsigned long long va = keys[t], vb = keys[ixj];
                    bool up = ((t & k) == 0);
                    if ((va > vb) == up) { keys[t] = vb; keys[ixj] = va; }
                }
            }
            __syncthreads();
        }
    }

    // --- gather boxes for top-NPRE ---
    for (int t = tid; t < NPRE; t += 1024) {
        int idx = (int)(unsigned int)(keys[t] & 0xFFFFFFFFull);
        sboxes[t] = *reinterpret_cast<const float4*>(&g_boxes[((size_t)b * NANCH + idx) * 4]);
        sup[t] = 0;
    }
    __syncthreads();

    // --- greedy NMS (matches reference scan semantics) ---
    for (int i = 0; i < NPRE; i++) {
        __syncthreads();
        if (sup[i]) continue;  // uniform across block after sync
        float4 bi = sboxes[i];
        float areai = (bi.z - bi.x) * (bi.w - bi.y);
        for (int j2 = i + 1 + tid; j2 < NPRE; j2 += 1024) {
            if (sup[j2]) continue;
            float4 bj = sboxes[j2];
            float iy = fmaxf(fminf(bi.z, bj.z) - fmaxf(bi.x, bj.x), 0.f);
            float ixl = fmaxf(fminf(bi.w, bj.w) - fmaxf(bi.y, bj.y), 0.f);
            float inter = iy * ixl;
            float areaj = (bj.z - bj.x) * (bj.w - bj.y);
            float iou = inter / (areai + areaj - inter + 1e-9f);
            if (iou > NMS_THRESH) sup[j2] = 1;
        }
    }
    __syncthreads();

    // --- emit: kept (in order) then suppressed (in order), first NPOST ---
    // This matches top_k(where(keep, top_s, -inf), NPOST) exactly (ties by index).
    if (tid == 0) {
        int pos = 0;
        for (int i = 0; i < NPRE && pos < NPOST; i++) {
            if (!sup[i]) {
                float4 bx = sboxes[i];
                float* o = out + ROIS_OFF + ((size_t)b * NPOST + pos) * 4;
                o[0] = bx.x; o[1] = bx.y; o[2] = bx.z; o[3] = bx.w;
                pos++;
            }
        }
        for (int i = 0; i < NPRE && pos < NPOST; i++) {
            if (sup[i]) {
                float4 bx = sboxes[i];
                float* o = out + ROIS_OFF + ((size_t)b * NPOST + pos) * 4;
                o[0] = bx.x; o[1] = bx.y; o[2] = bx.z; o[3] = bx.w;
                pos++;
            }
        }
    }
}

// ================= launch =================
extern "C" void kernel_launch(void* const* d_in, const int* in_sizes, int n_in,
                              void* d_out, int out_size) {
    const float* x  = (const float*)d_in[0];
    const float* W1 = (const float*)d_in[1];
    const float* b1 = (const float*)d_in[2];
    const float* Wl = (const float*)d_in[3];
    const float* bl = (const float*)d_in[4];
    const float* Ws = (const float*)d_in[5];
    const float* bs = (const float*)d_in[6];
    float* out = (float*)d_out;

    dim3 gconv((PIX + 127) / 128, MIDC / 128, BB);   // 20 x 4 x 4
    conv3x3_relu<<<gconv, 256>>>(x, W1, b1);

    int tot = BB * 54 * PIX;
    heads_kernel<<<(tot + 255) / 256, 256>>>(Wl, bl, Ws, bs, out);

    int tot2 = BB * NANCH;
    prep_kernel<<<(tot2 + 255) / 256, 256>>>(out);

    propose_kernel<<<BB, 1024>>>(out);
}

// round 2
// speedup vs baseline: 1.0045x; 1.0045x over previous
#include <cuda_runtime.h>
#include <math.h>

// ---------------- problem constants ----------------
#define BB 4
#define CIN 512
#define MIDC 512
#define PIX 2500
#define KTOT 4608          // 512*9
#define AA 9
#define NANCH 22500        // 2500*9
#define NPRE 1200
#define NPOST 300
#define IMGSZ 800.0f
#define NMS_THRESH 0.7f
#define MINSZ 16.0f

#define LOCS_OFF   0
#define SCORES_OFF 360000  // 4*22500*4
#define ROIS_OFF   540000  // + 4*22500*2

#define NWORDS 38          // ceil(1200/32)

// ---------------- scratch ----------------
__device__ float g_h[BB * MIDC * PIX];        // conv1 output (relu), [b][c][p]
__device__ float g_s[BB * NANCH];             // filtered fg scores
__device__ float g_boxes[BB * NANCH * 4];     // clipped candidate boxes

// ================= Kernel 1: 3x3 conv + bias + relu (implicit GEMM, fp32) =================
__global__ __launch_bounds__(256) void conv3x3_relu(const float* __restrict__ X,
                                                    const float* __restrict__ W1,
                                                    const float* __restrict__ b1) {
    __shared__ float As[16][128];
    __shared__ float Bs[16][128];

    const int b = blockIdx.z;
    const int mBase = blockIdx.y * 128;
    const int nBase = blockIdx.x * 128;
    const int tid = threadIdx.x;
    const int ty = tid >> 4;
    const int tx = tid & 15;

    float acc[8][8];
#pragma unroll
    for (int i = 0; i < 8; i++)
#pragma unroll
        for (int j = 0; j < 8; j++) acc[i][j] = 0.f;

    const int nb  = tid & 127;
    const int kb0 = tid >> 7;
    const int n_g = nBase + nb;
    const int y0  = n_g / 50;
    const int x0  = n_g - y0 * 50;
    const bool nvalid = (n_g < PIX);
    const float* Xb = X + (size_t)b * CIN * PIX;

    for (int k0 = 0; k0 < KTOT; k0 += 16) {
        {
            int m  = tid >> 2;
            int kq = (tid & 3) << 2;
#pragma unroll
            for (int mm = 0; mm < 2; mm++) {
                int mr = m + mm * 64;
                float4 v = *reinterpret_cast<const float4*>(
                    &W1[(size_t)(mBase + mr) * KTOT + k0 + kq]);
                As[kq + 0][mr] = v.x;
                As[kq + 1][mr] = v.y;
                As[kq + 2][mr] = v.z;
                As[kq + 3][mr] = v.w;
            }
        }
#pragma unroll
        for (int j = 0; j < 8; j++) {
            int k  = kb0 + (j << 1);
            int kg = k0 + k;
            int c  = kg / 9;
            int r  = kg - c * 9;
            int ry = r / 3;
            int rx = r - ry * 3;
            int yy = y0 + ry - 1;
            int xx = x0 + rx - 1;
            float v = 0.f;
            if (nvalid && (unsigned)yy < 50u && (unsigned)xx < 50u)
                v = __ldg(&Xb[c * PIX + yy * 50 + xx]);
            Bs[k][nb] = v;
        }
        __syncthreads();

#pragma unroll
        for (int kk = 0; kk < 16; kk++) {
            float4 a0 = *reinterpret_cast<float4*>(&As[kk][ty * 8]);
            float4 a1 = *reinterpret_cast<float4*>(&As[kk][ty * 8 + 4]);
            float4 c0 = *reinterpret_cast<float4*>(&Bs[kk][tx * 8]);
            float4 c1 = *reinterpret_cast<float4*>(&Bs[kk][tx * 8 + 4]);
            float av[8] = {a0.x, a0.y, a0.z, a0.w, a1.x, a1.y, a1.z, a1.w};
            float bv[8] = {c0.x, c0.y, c0.z, c0.w, c1.x, c1.y, c1.z, c1.w};
#pragma unroll
            for (int i = 0; i < 8; i++)
#pragma unroll
                for (int j = 0; j < 8; j++) acc[i][j] = fmaf(av[i], bv[j], acc[i][j]);
        }
        __syncthreads();
    }

#pragma unroll
    for (int i = 0; i < 8; i++) {
        int m = mBase + ty * 8 + i;
        float bias = b1[m];
#pragma unroll
        for (int jj = 0; jj < 8; jj += 4) {
            int n = nBase + tx * 8 + jj;
            if (n < PIX) {
                float4 v;
                v.x = fmaxf(acc[i][jj + 0] + bias, 0.f);
                v.y = fmaxf(acc[i][jj + 1] + bias, 0.f);
                v.z = fmaxf(acc[i][jj + 2] + bias, 0.f);
                v.w = fmaxf(acc[i][jj + 3] + bias, 0.f);
                *reinterpret_cast<float4*>(&g_h[(size_t)(b * MIDC + m) * PIX + n]) = v;
            }
        }
    }
}

// ================= Kernel 2: 1x1 heads, register-accumulated (h read once) =================
// block = 128 threads, each thread owns 1 pixel, accumulates all 54 output channels.
__global__ __launch_bounds__(128) void heads_kernel(const float* __restrict__ Wl,
                                                    const float* __restrict__ bl,
                                                    const float* __restrict__ Ws,
                                                    const float* __restrict__ bs,
                                                    float* __restrict__ out) {
    __shared__ float wsh[64 * 56];   // [cc][oc], oc padded to 56 (16B-aligned rows)
    __shared__ float bsm[54];

    const int b = blockIdx.y;
    const int p = blockIdx.x * 128 + threadIdx.x;
    const int tid = threadIdx.x;

    if (tid < 36) bsm[tid] = bl[tid];
    else if (tid < 54) bsm[tid] = bs[tid - 36];

    float4 acc4[14];
#pragma unroll
    for (int q = 0; q < 14; q++) acc4[q] = make_float4(0.f, 0.f, 0.f, 0.f);

    const float* hb = g_h + (size_t)(b * MIDC) * PIX;

    for (int c0 = 0; c0 < MIDC; c0 += 64) {
        __syncthreads();
        for (int idx = tid; idx < 64 * 56; idx += 128) {
            int cc = idx / 56, oc = idx - cc * 56;
            int c = c0 + cc;
            float v = 0.f;
            if (oc < 36) v = Wl[oc * MIDC + c];
            else if (oc < 54) v = Ws[(oc - 36) * MIDC + c];
            wsh[idx] = v;
        }
        __syncthreads();
        if (p < PIX) {
#pragma unroll 4
            for (int cc = 0; cc < 64; cc++) {
                float hv = __ldg(&hb[(size_t)(c0 + cc) * PIX + p]);
                const float4* wrow = reinterpret_cast<const float4*>(&wsh[cc * 56]);
#pragma unroll
                for (int q = 0; q < 14; q++) {
                    float4 wv = wrow[q];
                    acc4[q].x = fmaf(hv, wv.x, acc4[q].x);
                    acc4[q].y = fmaf(hv, wv.y, acc4[q].y);
                    acc4[q].z = fmaf(hv, wv.z, acc4[q].z);
                    acc4[q].w = fmaf(hv, wv.w, acc4[q].w);
                }
            }
        }
    }

    if (p < PIX) {
        const float* accf = reinterpret_cast<const float*>(acc4);
#pragma unroll
        for (int oc = 0; oc < 54; oc++) {
            float v = accf[oc] + bsm[oc];
            if (oc < 36) {
                int a = oc >> 2, d = oc & 3;
                out[LOCS_OFF + ((size_t)b * NANCH + p * AA + a) * 4 + d] = v;
            } else {
                int o = oc - 36;
                int a = o >> 1, cc2 = o & 1;
                out[SCORES_OFF + ((size_t)b * NANCH + p * AA + a) * 2 + cc2] = v;
            }
        }
    }
}

// ================= Kernel 3: per-anchor prep =================
__global__ void prep_kernel(const float* __restrict__ out) {
    int idx = blockIdx.x * blockDim.x + threadIdx.x;
    if (idx >= BB * NANCH) return;
    int i = idx % NANCH;

    float s0 = out[SCORES_OFF + (size_t)idx * 2 + 0];
    float s1 = out[SCORES_OFF + (size_t)idx * 2 + 1];
    float m  = fmaxf(s0, s1);
    float e0 = expf(s0 - m), e1 = expf(s1 - m);
    float fg = e1 / (e0 + e1);

    int p  = i / AA, a = i - (i / AA) * AA;
    int iy = p / 50, ix = p - iy * 50;
    const double ratios[3] = {0.5, 1.0, 2.0};
    const double scales[3] = {8.0, 16.0, 32.0};
    int ri = a / 3;
    double r  = ratios[ri];
    double sc = scales[a - ri * 3];
    double hhd = 16.0 * sc * sqrt(r);
    double wwd = 16.0 * sc * sqrt(1.0 / r);
    float y1b = (float)(8.0 - hhd * 0.5);
    float x1b = (float)(8.0 - wwd * 0.5);
    float y2b = (float)(8.0 + hhd * 0.5);
    float x2b = (float)(8.0 + wwd * 0.5);
    float sy = (float)(iy * 16), sx = (float)(ix * 16);
    float ay1 = sy + y1b, ax1 = sx + x1b, ay2 = sy + y2b, ax2 = sx + x2b;

    float ha = ay2 - ay1, wa = ax2 - ax1;
    float cy = ay1 + 0.5f * ha, cx = ax1 + 0.5f * wa;

    const float* lp = out + LOCS_OFF + (size_t)idx * 4;
    float dy = lp[0], dx = lp[1], dh = lp[2], dw = lp[3];
    float ncy = dy * ha + cy;
    float ncx = dx * wa + cx;
    float nh = expf(dh) * ha;
    float nw = expf(dw) * wa;

    float y1 = fminf(fmaxf(ncy - 0.5f * nh, 0.f), IMGSZ);
    float x1 = fminf(fmaxf(ncx - 0.5f * nw, 0.f), IMGSZ);
    float y2 = fminf(fmaxf(ncy + 0.5f * nh, 0.f), IMGSZ);
    float x2 = fminf(fmaxf(ncx + 0.5f * nw, 0.f), IMGSZ);

    *reinterpret_cast<float4*>(&g_boxes[(size_t)idx * 4]) = make_float4(y1, x1, y2, x2);
    float hs = y2 - y1, ws2 = x2 - x1;
    g_s[idx] = (hs >= MINSZ && ws2 >= MINSZ) ? fg : -INFINITY;
}

// ================= Kernel 4: per-batch propose =================
__device__ __forceinline__ unsigned long long make_key(float s, int i) {
    unsigned int u = __float_as_uint(s);
    u = (u & 0x80000000u) ? ~u : (u | 0x80000000u);
    unsigned int inv = ~u;                            // ascending == score descending
    return (((unsigned long long)inv) << 32) | (unsigned int)i;
}

// dynamic smem layout (bytes):
//   [0,      19200)  : sboxes  float4[1200]
//   [19200,  35584)  : keys    u64[2048]      } dead after gather;
//   [35584,  43776)  : hist    u32[2048]      } aliased by mask
//   [19200, 201600)  : mask    u32[1200*38]
#define OFF_KEYS 19200
#define OFF_HIST 35584
#define OFF_MASK 19200
#define DYN_SMEM 201600

__global__ __launch_bounds__(1024) void propose_kernel(float* __restrict__ out) {
    extern __shared__ unsigned char dyn[];
    float4* sboxes = reinterpret_cast<float4*>(dyn);
    unsigned long long* keys = reinterpret_cast<unsigned long long*>(dyn + OFF_KEYS);
    unsigned int* hist = reinterpret_cast<unsigned int*>(dyn + OFF_HIST);
    unsigned int* umask = reinterpret_cast<unsigned int*>(dyn + OFF_MASK);

    __shared__ unsigned long long sh_prefix;
    __shared__ int sh_rem, sh_cnt, sh_done, sh_total;
    __shared__ unsigned int keepw[NWORDS];
    __shared__ unsigned int kpre[NWORDS + 1];

    const int b = blockIdx.x;
    const int tid = threadIdx.x;
    const int lane = tid & 31;
    const int wid = tid >> 5;
    const float* sb = g_s + (size_t)b * NANCH;

    // --- radix select with early exit ---
    unsigned long long prefix = 0ull;
    int pb = 0;
    int remaining = NPRE - 1;
    const int widths[6] = {11, 11, 11, 11, 11, 9};
    if (tid == 0) sh_done = 0;
    __syncthreads();
    for (int pass = 0; pass < 6; pass++) {
        int w  = widths[pass];
        int nbk = 1 << w;
        for (int t = tid; t < 2048; t += 1024) hist[t] = 0;
        __syncthreads();
        int shift = 64 - pb - w;
        for (int i = tid; i < NANCH; i += 1024) {
            unsigned long long key = make_key(sb[i], i);
            bool match = (pb == 0) || ((key >> (64 - pb)) == prefix);
            if (match) {
                unsigned int d = (unsigned int)((key >> shift) & (unsigned long long)(nbk - 1));
                atomicAdd(&hist[d], 1u);
            }
        }
        __syncthreads();
        if (tid == 0) {
            unsigned int cum = 0;
            for (int d = 0; d < nbk; d++) {
                unsigned int c = hist[d];
                if (cum + c > (unsigned int)remaining) {
                    sh_prefix = (prefix << w) | (unsigned long long)d;
                    sh_rem = remaining - (int)cum;
                    int count_less = (NPRE - 1) - (remaining - (int)cum);
                    sh_total = count_less + (int)c;
                    if (count_less + (int)c <= 2048) sh_done = 1;
                    break;
                }
                cum += c;
            }
        }
        __syncthreads();
        prefix = sh_prefix;
        remaining = sh_rem;
        pb += w;
        if (sh_done) break;
        __syncthreads();
    }

    // --- compact candidates: high-bits <= prefix (count == sh_total <= 2048) ---
    if (tid == 0) sh_cnt = 0;
    __syncthreads();
    {
        int s = 64 - pb;   // 0..53
        for (int i = tid; i < NANCH; i += 1024) {
            unsigned long long key = make_key(sb[i], i);
            unsigned long long hb = key >> s;
            if (hb <= prefix) {
                int pos = atomicAdd(&sh_cnt, 1);
                if (pos < 2048) keys[pos] = key;
            }
        }
    }
    __syncthreads();
    int cnt = sh_cnt;
    if (cnt > 2048) cnt = 2048;
    for (int t = tid; t < 2048; t += 1024)
        if (t >= cnt) keys[t] = 0xFFFFFFFFFFFFFFFFull;
    __syncthreads();

    // --- bitonic sort ascending (2048) -> score desc, index asc ---
    for (int k = 2; k <= 2048; k <<= 1) {
        for (int j = k >> 1; j > 0; j >>= 1) {
            for (int t = tid; t < 2048; t += 1024) {
                int ixj = t ^ j;
                if (ixj > t) {
                    unsigned long long va = keys[t], vb = keys[ixj];
                    bool up = ((t & k) == 0);
                    if ((va > vb) == up) { keys[t] = vb; keys[ixj] = va; }
                }
            }
            __syncthreads();
        }
    }

    // --- gather top-NPRE boxes ---
    for (int t = tid; t < NPRE; t += 1024) {
        int idx = (int)(unsigned int)(keys[t] & 0xFFFFFFFFull);
        sboxes[t] = *reinterpret_cast<const float4*>(&g_boxes[((size_t)b * NANCH + idx) * 4]);
    }
    __syncthreads();   // keys dead; umask may now overwrite that region

    // --- parallel IoU bitmask: umask[i*38+w] bit (j&31) = iou(i, j=w*32+lane) > th, j>i ---
    for (int t = wid; t < NPRE * NWORDS; t += 32) {
        int i = t / NWORDS, w = t - i * NWORDS;
        if ((w << 5) + 31 <= i) continue;     // word entirely below/at i: never read
        float4 bi = sboxes[i];
        float areai = (bi.z - bi.x) * (bi.w - bi.y);
        int j = (w << 5) + lane;
        unsigned int pred = 0;
        if (j > i && j < NPRE) {
            float4 bj = sboxes[j];
            float iy  = fmaxf(fminf(bi.z, bj.z) - fmaxf(bi.x, bj.x), 0.f);
            float ixl = fmaxf(fminf(bi.w, bj.w) - fmaxf(bi.y, bj.y), 0.f);
            float inter = iy * ixl;
            float areaj = (bj.z - bj.x) * (bj.w - bj.y);
            float iou = inter / (areai + areaj - inter + 1e-9f);
            pred = (iou > NMS_THRESH) ? 1u : 0u;
        }
        unsigned int word = __ballot_sync(0xffffffffu, pred);
        if (lane == 0) umask[i * NWORDS + w] = word;
    }
    __syncthreads();

    // --- single-warp greedy sweep over bitmask ---
    if (wid == 0) {
        unsigned int sup0 = 0, sup1 = 0;    // lane holds word 'lane' and word '32+lane' (lane<6)
        unsigned int kb0 = 0, kb1 = 0;
        for (int i = 0; i < NPRE; i++) {
            int w = i >> 5, bit = i & 31;
            unsigned int v = (w < 32) ? sup0 : sup1;
            int src = (w < 32) ? w : (w - 32);
            unsigned int word = __shfl_sync(0xffffffffu, v, src);
            if (!((word >> bit) & 1u)) {
                if (lane == src) { if (w < 32) kb0 |= (1u << bit); else kb1 |= (1u << bit); }
                sup0 |= umask[i * NWORDS + lane];
                if (lane < NWORDS - 32) sup1 |= umask[i * NWORDS + 32 + lane];
            }
        }
        keepw[lane] = kb0;
        if (lane < NWORDS - 32) keepw[32 + lane] = kb1;
    }
    __syncthreads();

    if (tid == 0) {
        unsigned int s = 0;
        for (int w = 0; w < NWORDS; w++) { kpre[w] = s; s += __popc(keepw[w]); }
        kpre[NWORDS] = s;
    }
    __syncthreads();

    // --- emit: kept in order, then suppressed in order (rank via popc prefix) ---
    int nkept = kpre[NWORDS];
    for (int t = tid; t < NPRE; t += 1024) {
        int w = t >> 5, bit = t & 31;
        bool kp = (keepw[w] >> bit) & 1u;
        int keptBefore = kpre[w] + __popc(keepw[w] & ((1u << bit) - 1u));
        int rank = kp ? keptBefore : nkept + (t - keptBefore);
        if (rank < NPOST) {
            float4 bx = sboxes[t];
            *reinterpret_cast<float4*>(&out[ROIS_OFF + ((size_t)b * NPOST + rank) * 4]) = bx;
        }
    }
}

// ================= launch =================
extern "C" void kernel_launch(void* const* d_in, const int* in_sizes, int n_in,
                              void* d_out, int out_size) {
    const float* x  = (const float*)d_in[0];
    const float* W1 = (const float*)d_in[1];
    const float* b1 = (const float*)d_in[2];
    const float* Wl = (const float*)d_in[3];
    const float* bl = (const float*)d_in[4];
    const float* Ws = (const float*)d_in[5];
    const float* bs = (const float*)d_in[6];
    float* out = (float*)d_out;

    dim3 gconv((PIX + 127) / 128, MIDC / 128, BB);
    conv3x3_relu<<<gconv, 256>>>(x, W1, b1);

    dim3 gheads((PIX + 127) / 128, BB);
    heads_kernel<<<gheads, 128>>>(Wl, bl, Ws, bs, out);

    int tot2 = BB * NANCH;
    prep_kernel<<<(tot2 + 255) / 256, 256>>>(out);

    static int smem_set = 0;
    (void)smem_set;
    cudaFuncSetAttribute(propose_kernel, cudaFuncAttributeMaxDynamicSharedMemorySize, DYN_SMEM);
    propose_kernel<<<BB, 1024, DYN_SMEM>>>(out);
}

// round 3
// speedup vs baseline: 1.2650x; 1.2593x over previous
#include <cuda_runtime.h>
#include <math.h>

// ---------------- problem constants ----------------
#define BB 4
#define CIN 512
#define MIDC 512
#define PIX 2500
#define KTOT 4608          // 512*9
#define AA 9
#define NANCH 22500        // 2500*9
#define NPRE 1200
#define NPOST 300
#define IMGSZ 800.0f
#define NMS_THRESH 0.7f
#define MINSZ 16.0f

#define LOCS_OFF   0
#define SCORES_OFF 360000  // 4*22500*4
#define ROIS_OFF   540000  // + 4*22500*2

#define NWORDS 38          // ceil(1200/32)

// ---------------- scratch ----------------
__device__ float g_h[BB * MIDC * PIX];        // conv1 output (relu), [b][c][p]
__device__ float g_s[BB * NANCH];             // filtered fg scores
__device__ float g_boxes[BB * NANCH * 4];     // clipped candidate boxes

// ---------------- packed f32x2 helpers ----------------
__device__ __forceinline__ void fma2(unsigned long long& acc, unsigned long long a,
                                     unsigned long long b) {
    asm("fma.rn.f32x2 %0, %1, %2, %0;" : "+l"(acc) : "l"(a), "l"(b));
}
__device__ __forceinline__ unsigned long long dup2(float v) {
    unsigned long long d;
    asm("mov.b64 %0, {%1, %1};" : "=l"(d) : "f"(v));
    return d;
}
__device__ __forceinline__ float lo32(unsigned long long u) {
    return __uint_as_float((unsigned int)(u & 0xffffffffull));
}
__device__ __forceinline__ float hi32(unsigned long long u) {
    return __uint_as_float((unsigned int)(u >> 32));
}

// ================= Kernel 1: 3x3 conv + bias + relu (implicit GEMM, FFMA2) =================
__global__ __launch_bounds__(256) void conv3x3_relu(const float* __restrict__ X,
                                                    const float* __restrict__ W1,
                                                    const float* __restrict__ b1) {
    __shared__ float As[16][128];
    __shared__ float Bs[16][128];

    const int b = blockIdx.z;
    const int mBase = blockIdx.y * 128;
    const int nBase = blockIdx.x * 128;
    const int tid = threadIdx.x;
    const int ty = tid >> 4;
    const int tx = tid & 15;

    // acc2[i][q] holds output pair (j = 2q, 2q+1) for row i of the 8x8 tile
    unsigned long long acc2[8][4];
#pragma unroll
    for (int i = 0; i < 8; i++)
#pragma unroll
        for (int q = 0; q < 4; q++) acc2[i][q] = 0ull;

    const int nb  = tid & 127;
    const int kb0 = tid >> 7;
    const int n_g = nBase + nb;
    const int y0  = n_g / 50;
    const int x0  = n_g - y0 * 50;
    const bool nvalid = (n_g < PIX);
    const float* Xb = X + (size_t)b * CIN * PIX;

    for (int k0 = 0; k0 < KTOT; k0 += 16) {
        {
            int m  = tid >> 2;
            int kq = (tid & 3) << 2;
#pragma unroll
            for (int mm = 0; mm < 2; mm++) {
                int mr = m + mm * 64;
                float4 v = *reinterpret_cast<const float4*>(
                    &W1[(size_t)(mBase + mr) * KTOT + k0 + kq]);
                As[kq + 0][mr] = v.x;
                As[kq + 1][mr] = v.y;
                As[kq + 2][mr] = v.z;
                As[kq + 3][mr] = v.w;
            }
        }
#pragma unroll
        for (int j = 0; j < 8; j++) {
            int k  = kb0 + (j << 1);
            int kg = k0 + k;
            int c  = kg / 9;
            int r  = kg - c * 9;
            int ry = r / 3;
            int rx = r - ry * 3;
            int yy = y0 + ry - 1;
            int xx = x0 + rx - 1;
            float v = 0.f;
            if (nvalid && (unsigned)yy < 50u && (unsigned)xx < 50u)
                v = __ldg(&Xb[c * PIX + yy * 50 + xx]);
            Bs[k][nb] = v;
        }
        __syncthreads();

#pragma unroll
        for (int kk = 0; kk < 16; kk++) {
            float4 a0 = *reinterpret_cast<float4*>(&As[kk][ty * 8]);
            float4 a1 = *reinterpret_cast<float4*>(&As[kk][ty * 8 + 4]);
            ulonglong2 q0 = *reinterpret_cast<ulonglong2*>(&Bs[kk][tx * 8]);
            ulonglong2 q1 = *reinterpret_cast<ulonglong2*>(&Bs[kk][tx * 8 + 4]);
            float av[8] = {a0.x, a0.y, a0.z, a0.w, a1.x, a1.y, a1.z, a1.w};
#pragma unroll
            for (int i = 0; i < 8; i++) {
                unsigned long long ad = dup2(av[i]);
                fma2(acc2[i][0], ad, q0.x);
                fma2(acc2[i][1], ad, q0.y);
                fma2(acc2[i][2], ad, q1.x);
                fma2(acc2[i][3], ad, q1.y);
            }
        }
        __syncthreads();
    }

#pragma unroll
    for (int i = 0; i < 8; i++) {
        int m = mBase + ty * 8 + i;
        float bias = b1[m];
#pragma unroll
        for (int q = 0; q < 4; q += 2) {
            int n = nBase + tx * 8 + q * 2;
            if (n < PIX) {
                float4 v;
                v.x = fmaxf(lo32(acc2[i][q])     + bias, 0.f);
                v.y = fmaxf(hi32(acc2[i][q])     + bias, 0.f);
                v.z = fmaxf(lo32(acc2[i][q + 1]) + bias, 0.f);
                v.w = fmaxf(hi32(acc2[i][q + 1]) + bias, 0.f);
                *reinterpret_cast<float4*>(&g_h[(size_t)(b * MIDC + m) * PIX + n]) = v;
            }
        }
    }
}

// ================= Kernel 2: 1x1 heads (FFMA2, h read once) =================
__global__ __launch_bounds__(128) void heads_kernel(const float* __restrict__ Wl,
                                                    const float* __restrict__ bl,
                                                    const float* __restrict__ Ws,
                                                    const float* __restrict__ bs,
                                                    float* __restrict__ out) {
    __shared__ float wsh[64 * 56];   // [cc][oc], oc padded to 56
    __shared__ float bsm[54];

    const int b = blockIdx.y;
    const int p = blockIdx.x * 128 + threadIdx.x;
    const int tid = threadIdx.x;

    if (tid < 36) bsm[tid] = bl[tid];
    else if (tid < 54) bsm[tid] = bs[tid - 36];

    unsigned long long acc2[28];
#pragma unroll
    for (int q = 0; q < 28; q++) acc2[q] = 0ull;

    const float* hb = g_h + (size_t)(b * MIDC) * PIX;

    for (int c0 = 0; c0 < MIDC; c0 += 64) {
        __syncthreads();
        for (int idx = tid; idx < 64 * 56; idx += 128) {
            int cc = idx / 56, oc = idx - cc * 56;
            int c = c0 + cc;
            float v = 0.f;
            if (oc < 36) v = Wl[oc * MIDC + c];
            else if (oc < 54) v = Ws[(oc - 36) * MIDC + c];
            wsh[idx] = v;
        }
        __syncthreads();
        if (p < PIX) {
#pragma unroll 4
            for (int cc = 0; cc < 64; cc++) {
                float hv = __ldg(&hb[(size_t)(c0 + cc) * PIX + p]);
                unsigned long long hd = dup2(hv);
                const ulonglong2* wrow = reinterpret_cast<const ulonglong2*>(&wsh[cc * 56]);
#pragma unroll
                for (int q = 0; q < 14; q++) {
                    ulonglong2 wp = wrow[q];
                    fma2(acc2[q * 2 + 0], hd, wp.x);
                    fma2(acc2[q * 2 + 1], hd, wp.y);
                }
            }
        }
    }

    if (p < PIX) {
#pragma unroll
        for (int oc = 0; oc < 54; oc++) {
            unsigned long long u = acc2[oc >> 1];
            float v = ((oc & 1) ? hi32(u) : lo32(u)) + bsm[oc];
            if (oc < 36) {
                int a = oc >> 2, d = oc & 3;
                out[LOCS_OFF + ((size_t)b * NANCH + p * AA + a) * 4 + d] = v;
            } else {
                int o = oc - 36;
                int a = o >> 1, cc2 = o & 1;
                out[SCORES_OFF + ((size_t)b * NANCH + p * AA + a) * 2 + cc2] = v;
            }
        }
    }
}

// ================= Kernel 3: per-anchor prep =================
__global__ void prep_kernel(const float* __restrict__ out) {
    int idx = blockIdx.x * blockDim.x + threadIdx.x;
    if (idx >= BB * NANCH) return;
    int i = idx % NANCH;

    float s0 = out[SCORES_OFF + (size_t)idx * 2 + 0];
    float s1 = out[SCORES_OFF + (size_t)idx * 2 + 1];
    float m  = fmaxf(s0, s1);
    float e0 = expf(s0 - m), e1 = expf(s1 - m);
    float fg = e1 / (e0 + e1);

    int p  = i / AA, a = i - (i / AA) * AA;
    int iy = p / 50, ix = p - iy * 50;
    const double ratios[3] = {0.5, 1.0, 2.0};
    const double scales[3] = {8.0, 16.0, 32.0};
    int ri = a / 3;
    double r  = ratios[ri];
    double sc = scales[a - ri * 3];
    double hhd = 16.0 * sc * sqrt(r);
    double wwd = 16.0 * sc * sqrt(1.0 / r);
    float y1b = (float)(8.0 - hhd * 0.5);
    float x1b = (float)(8.0 - wwd * 0.5);
    float y2b = (float)(8.0 + hhd * 0.5);
    float x2b = (float)(8.0 + wwd * 0.5);
    float sy = (float)(iy * 16), sx = (float)(ix * 16);
    float ay1 = sy + y1b, ax1 = sx + x1b, ay2 = sy + y2b, ax2 = sx + x2b;

    float ha = ay2 - ay1, wa = ax2 - ax1;
    float cy = ay1 + 0.5f * ha, cx = ax1 + 0.5f * wa;

    const float* lp = out + LOCS_OFF + (size_t)idx * 4;
    float dy = lp[0], dx = lp[1], dh = lp[2], dw = lp[3];
    float ncy = dy * ha + cy;
    float ncx = dx * wa + cx;
    float nh = expf(dh) * ha;
    float nw = expf(dw) * wa;

    float y1 = fminf(fmaxf(ncy - 0.5f * nh, 0.f), IMGSZ);
    float x1 = fminf(fmaxf(ncx - 0.5f * nw, 0.f), IMGSZ);
    float y2 = fminf(fmaxf(ncy + 0.5f * nh, 0.f), IMGSZ);
    float x2 = fminf(fmaxf(ncx + 0.5f * nw, 0.f), IMGSZ);

    *reinterpret_cast<float4*>(&g_boxes[(size_t)idx * 4]) = make_float4(y1, x1, y2, x2);
    float hs = y2 - y1, ws2 = x2 - x1;
    g_s[idx] = (hs >= MINSZ && ws2 >= MINSZ) ? fg : -INFINITY;
}

// ================= Kernel 4: per-batch propose =================
__device__ __forceinline__ unsigned long long make_key(float s, int i) {
    unsigned int u = __float_as_uint(s);
    u = (u & 0x80000000u) ? ~u : (u | 0x80000000u);
    unsigned int inv = ~u;                            // ascending == score descending
    return (((unsigned long long)inv) << 32) | (unsigned int)i;
}

// dynamic smem layout (bytes):
//   [0,      19200)  : sboxes  float4[1200]
//   [19200,  35584)  : keys    u64[2048]      } dead after gather;
//   [35584,  43776)  : hist    u32[2048]      } aliased by mask
//   [19200, 201600)  : mask    u32[1200*38]
#define OFF_KEYS 19200
#define OFF_HIST 35584
#define OFF_MASK 19200
#define DYN_SMEM 201600

__global__ __launch_bounds__(1024) void propose_kernel(float* __restrict__ out) {
    extern __shared__ unsigned char dyn[];
    float4* sboxes = reinterpret_cast<float4*>(dyn);
    unsigned long long* keys = reinterpret_cast<unsigned long long*>(dyn + OFF_KEYS);
    unsigned int* hist = reinterpret_cast<unsigned int*>(dyn + OFF_HIST);
    unsigned int* umask = reinterpret_cast<unsigned int*>(dyn + OFF_MASK);

    __shared__ unsigned long long sh_prefix;
    __shared__ int sh_rem, sh_cnt, sh_done;
    __shared__ unsigned int keepw[NWORDS];
    __shared__ unsigned int kpre[NWORDS + 1];

    const int b = blockIdx.x;
    const int tid = threadIdx.x;
    const int lane = tid & 31;
    const int wid = tid >> 5;
    const float* sb = g_s + (size_t)b * NANCH;

    // --- radix select with early exit (warp-aggregated histogram atomics) ---
    unsigned long long prefix = 0ull;
    int pb = 0;
    int remaining = NPRE - 1;
    const int widths[6] = {11, 11, 11, 11, 11, 9};
    if (tid == 0) sh_done = 0;
    __syncthreads();
    for (int pass = 0; pass < 6; pass++) {
        int w  = widths[pass];
        int nbk = 1 << w;
        for (int t = tid; t < 2048; t += 1024) hist[t] = 0;
        __syncthreads();
        int shift = 64 - pb - w;
        for (int i0 = tid; i0 < 23552; i0 += 1024) {   // padded multiple of 1024
            bool valid = (i0 < NANCH);
            unsigned int d = 0;
            if (valid) {
                unsigned long long key = make_key(sb[i0], i0);
                valid = (pb == 0) || ((key >> (64 - pb)) == prefix);
                d = (unsigned int)((key >> shift) & (unsigned long long)(nbk - 1));
            }
            unsigned int am = __ballot_sync(0xffffffffu, valid);
            if (valid) {
                unsigned int mm = __match_any_sync(am, d);
                if ((__ffs(mm) - 1) == lane) atomicAdd(&hist[d], (unsigned int)__popc(mm));
            }
        }
        __syncthreads();
        if (tid == 0) {
            unsigned int cum = 0;
            for (int d = 0; d < nbk; d++) {
                unsigned int c = hist[d];
                if (cum + c > (unsigned int)remaining) {
                    sh_prefix = (prefix << w) | (unsigned long long)d;
                    sh_rem = remaining - (int)cum;
                    int count_less = (NPRE - 1) - (remaining - (int)cum);
                    if (count_less + (int)c <= 2048) sh_done = 1;
                    break;
                }
                cum += c;
            }
        }
        __syncthreads();
        prefix = sh_prefix;
        remaining = sh_rem;
        pb += w;
        if (sh_done) break;
        __syncthreads();
    }

    // --- compact candidates (ballot-aggregated counter) ---
    if (tid == 0) sh_cnt = 0;
    __syncthreads();
    {
        int s = 64 - pb;
        for (int i0 = tid; i0 < 23552; i0 += 1024) {
            bool pred = false;
            unsigned long long key = 0;
            if (i0 < NANCH) {
                key = make_key(sb[i0], i0);
                pred = ((key >> s) <= prefix);
            }
            unsigned int bal = __ballot_sync(0xffffffffu, pred);
            int nset = __popc(bal);
            if (nset) {
                int base = 0;
                int leader = __ffs(bal) - 1;
                if (lane == leader) base = atomicAdd(&sh_cnt, nset);
                base = __shfl_sync(0xffffffffu, base, leader);
                if (pred) {
                    int pos = base + __popc(bal & ((1u << lane) - 1u));
                    if (pos < 2048) keys[pos] = key;
                }
            }
        }
    }
    __syncthreads();
    int cnt = sh_cnt;
    if (cnt > 2048) cnt = 2048;
    for (int t = tid; t < 2048; t += 1024)
        if (t >= cnt) keys[t] = 0xFFFFFFFFFFFFFFFFull;
    __syncthreads();

    // --- bitonic sort ascending (2048) -> score desc, index asc ---
    for (int k = 2; k <= 2048; k <<= 1) {
        for (int j = k >> 1; j > 0; j >>= 1) {
            for (int t = tid; t < 2048; t += 1024) {
                int ixj = t ^ j;
                if (ixj > t) {
                    unsigned long long va = keys[t], vb = keys[ixj];
                    bool up = ((t & k) == 0);
                    if ((va > vb) == up) { keys[t] = vb; keys[ixj] = va; }
                }
            }
            __syncthreads();
        }
    }

    // --- gather top-NPRE boxes ---
    for (int t = tid; t < NPRE; t += 1024) {
        int idx = (int)(unsigned int)(keys[t] & 0xFFFFFFFFull);
        sboxes[t] = *reinterpret_cast<const float4*>(&g_boxes[((size_t)b * NANCH + idx) * 4]);
    }
    __syncthreads();   // keys dead; umask aliases that region

    // --- parallel IoU bitmask: warp w owns rows i = w, w+32, ... (no division) ---
    for (int i = wid; i < NPRE; i += 32) {
        float4 bi = sboxes[i];
        float areai = (bi.z - bi.x) * (bi.w - bi.y);
        int w0 = i >> 5;
        for (int w = w0; w < NWORDS; w++) {
            int j = (w << 5) + lane;
            unsigned int pred = 0;
            if (j > i && j < NPRE) {
                float4 bj = sboxes[j];
                float iy  = fmaxf(fminf(bi.z, bj.z) - fmaxf(bi.x, bj.x), 0.f);
                float ixl = fmaxf(fminf(bi.w, bj.w) - fmaxf(bi.y, bj.y), 0.f);
                float inter = iy * ixl;
                float areaj = (bj.z - bj.x) * (bj.w - bj.y);
                float iou = inter / (areai + areaj - inter + 1e-9f);
                pred = (iou > NMS_THRESH) ? 1u : 0u;
            }
            unsigned int word = __ballot_sync(0xffffffffu, pred);
            if (lane == 0) umask[i * NWORDS + w] = word;
        }
    }
    __syncthreads();

    // --- single-warp greedy sweep over bitmask ---
    if (wid == 0) {
        unsigned int sup0 = 0, sup1 = 0;
        unsigned int kb0 = 0, kb1 = 0;
        for (int i = 0; i < NPRE; i++) {
            int w = i >> 5, bit = i & 31;
            unsigned int v = (w < 32) ? sup0 : sup1;
            int src = (w < 32) ? w : (w - 32);
            unsigned int word = __shfl_sync(0xffffffffu, v, src);
            if (!((word >> bit) & 1u)) {
                if (lane == src) { if (w < 32) kb0 |= (1u << bit); else kb1 |= (1u << bit); }
                sup0 |= umask[i * NWORDS + lane];
                if (lane < NWORDS - 32) sup1 |= umask[i * NWORDS + 32 + lane];
            }
        }
        keepw[lane] = kb0;
        if (lane < NWORDS - 32) keepw[32 + lane] = kb1;
    }
    __syncthreads();

    if (tid == 0) {
        unsigned int s = 0;
        for (int w = 0; w < NWORDS; w++) { kpre[w] = s; s += __popc(keepw[w]); }
        kpre[NWORDS] = s;
    }
    __syncthreads();

    // --- emit: kept in order, then suppressed in order ---
    int nkept = kpre[NWORDS];
    for (int t = tid; t < NPRE; t += 1024) {
        int w = t >> 5, bit = t & 31;
        bool kp = (keepw[w] >> bit) & 1u;
        int keptBefore = kpre[w] + __popc(keepw[w] & ((1u << bit) - 1u));
        int rank = kp ? keptBefore : nkept + (t - keptBefore);
        if (rank < NPOST) {
            float4 bx = sboxes[t];
            *reinterpret_cast<float4*>(&out[ROIS_OFF + ((size_t)b * NPOST + rank) * 4]) = bx;
        }
    }
}

// ================= launch =================
extern "C" void kernel_launch(void* const* d_in, const int* in_sizes, int n_in,
                              void* d_out, int out_size) {
    const float* x  = (const float*)d_in[0];
    const float* W1 = (const float*)d_in[1];
    const float* b1 = (const float*)d_in[2];
    const float* Wl = (const float*)d_in[3];
    const float* bl = (const float*)d_in[4];
    const float* Ws = (const float*)d_in[5];
    const float* bs = (const float*)d_in[6];
    float* out = (float*)d_out;

    dim3 gconv((PIX + 127) / 128, MIDC / 128, BB);
    conv3x3_relu<<<gconv, 256>>>(x, W1, b1);

    dim3 gheads((PIX + 127) / 128, BB);
    heads_kernel<<<gheads, 128>>>(Wl, bl, Ws, bs, out);

    int tot2 = BB * NANCH;
    prep_kernel<<<(tot2 + 255) / 256, 256>>>(out);

    cudaFuncSetAttribute(propose_kernel, cudaFuncAttributeMaxDynamicSharedMemorySize, DYN_SMEM);
    propose_kernel<<<BB, 1024, DYN_SMEM>>>(out);
}

// round 7
// speedup vs baseline: 1.3743x; 1.0864x over previous
#include <cuda_runtime.h>
#include <cuda_bf16.h>
#include <math.h>
#include <cstdint>

// ---------------- problem constants ----------------
#define BB 4
#define CIN 512
#define MIDC 512
#define PIX 2500
#define KTOT 4608          // 512*9
#define AA 9
#define NANCH 22500
#define NPRE 1200
#define NPOST 300
#define IMGSZ 800.0f
#define NMS_THRESH 0.7f
#define MINSZ 16.0f

#define LOCS_OFF   0
#define SCORES_OFF 360000
#define ROIS_OFF   540000

#define NWORDS 38

// conv mma tiling
#define NCH 288            // 4608/16 chunks of K=16
#define TILE_B 6144        // 128 rows x 48 bytes (16 bf16 data + 8 pad)
#define STAGE_BYTES 36864  // 6 tiles
#define CONV_SMEM (2 * STAGE_BYTES)  // 73728

#define WPL (MIDC * KTOT)
#define XPL (BB * PIX * CIN)

// ---------------- scratch ----------------
__device__ float g_h[BB * MIDC * PIX];
__device__ float g_s[BB * NANCH];
__device__ float g_boxes[BB * NANCH * 4];
__device__ __nv_bfloat16 g_wsp[3 * WPL];   // weight splits
__device__ __nv_bfloat16 g_xsp[3 * XPL];   // x splits

// ---------------- helpers ----------------
__device__ __forceinline__ uint32_t smem_u32(const void* p) {
    uint32_t a;
    asm("{ .reg .u64 t; cvta.to.shared.u64 t, %1; cvt.u32.u64 %0, t; }" : "=r"(a) : "l"(p));
    return a;
}
__device__ __forceinline__ void cp16(uint32_t dst, const void* src, int sz) {
    asm volatile("cp.async.ca.shared.global [%0], [%1], 16, %2;"
                 :: "r"(dst), "l"(src), "r"(sz) : "memory");
}
#define CP_COMMIT() asm volatile("cp.async.commit_group;" ::: "memory")
#define CP_WAIT1()  asm volatile("cp.async.wait_group 1;" ::: "memory")
#define CP_WAIT0()  asm volatile("cp.async.wait_group 0;" ::: "memory")

__device__ __forceinline__ void mma_bf16(float* d, const uint32_t* a, const uint32_t* bf) {
    asm volatile(
        "mma.sync.aligned.m16n8k16.row.col.f32.bf16.bf16.f32 "
        "{%0,%1,%2,%3}, {%4,%5,%6,%7}, {%8,%9}, {%0,%1,%2,%3};"
        : "+f"(d[0]), "+f"(d[1]), "+f"(d[2]), "+f"(d[3])
        : "r"(a[0]), "r"(a[1]), "r"(a[2]), "r"(a[3]), "r"(bf[0]), "r"(bf[1]));
}

__device__ __forceinline__ void bf16_split3(float v, __nv_bfloat16& s0,
                                            __nv_bfloat16& s1, __nv_bfloat16& s2) {
    __nv_bfloat16 b0 = __float2bfloat16_rn(v);
    float r1 = v - __bfloat162float(b0);
    __nv_bfloat16 b1 = __float2bfloat16_rn(r1);
    float r2 = r1 - __bfloat162float(b1);
    __nv_bfloat16 b2 = __float2bfloat16_rn(r2);
    s0 = b0; s1 = b1; s2 = b2;
}

// ================= prep: weight reorder + bf16 3-split =================
__global__ void prep_w(const float* __restrict__ W1) {
    int idx = blockIdx.x * 256 + threadIdx.x;
    if (idx >= WPL) return;
    int oc = idx / KTOT, kn = idx - oc * KTOT;
    int r = kn >> 9, c = kn & 511;
    float v = W1[(size_t)oc * KTOT + c * 9 + r];
    __nv_bfloat16 s0, s1, s2;
    bf16_split3(v, s0, s1, s2);
    g_wsp[idx] = s0;
    g_wsp[WPL + idx] = s1;
    g_wsp[2 * WPL + idx] = s2;
}

// ================= prep: X NCHW -> NHWC + bf16 3-split =================
__global__ void prep_x(const float* __restrict__ X) {
    __shared__ float t[32][33];
    int b = blockIdx.z;
    int p0 = blockIdx.x * 32;
    int c0 = blockIdx.y * 32;
    int tx = threadIdx.x, ty = threadIdx.y;
    const float* Xb = X + ((size_t)b * CIN + c0) * PIX;
#pragma unroll
    for (int k = 0; k < 32; k += 8) {
        int p = p0 + tx;
        t[ty + k][tx] = (p < PIX) ? Xb[(size_t)(ty + k) * PIX + p] : 0.f;
    }
    __syncthreads();
#pragma unroll
    for (int k = 0; k < 32; k += 8) {
        int p = p0 + ty + k;
        if (p < PIX) {
            float v = t[tx][ty + k];
            __nv_bfloat16 s0, s1, s2;
            bf16_split3(v, s0, s1, s2);
            size_t o = ((size_t)b * PIX + p) * CIN + c0 + tx;
            g_xsp[o] = s0;
            g_xsp[XPL + o] = s1;
            g_xsp[2 * XPL + o] = s2;
        }
    }
}

// ================= Kernel 1: conv3x3+relu, BF16x6 MMA + segmented accumulation ========
__global__ __launch_bounds__(256) void conv_mma(const float* __restrict__ b1) {
    extern __shared__ char smc[];

    const int b = blockIdx.z;
    const int mBase = blockIdx.y * 128;
    const int nBase = blockIdx.x * 128;
    const int tid = threadIdx.x;
    const int wid = tid >> 5;
    const int lane = tid & 31;
    const int lr = lane >> 2;
    const int lc = lane & 3;

    const int wm = (wid & 1) * 64;
    const int wn = (wid >> 1) * 32;

    const uint32_t sbase = smem_u32(smc);

    float acc[4][4][4];    // per-chunk accumulator (reset each chunk)
    float tot[4][4][4];    // running total (one FADD per chunk per value)
#pragma unroll
    for (int mi = 0; mi < 4; mi++)
#pragma unroll
        for (int ni = 0; ni < 4; ni++)
#pragma unroll
            for (int q = 0; q < 4; q++) { acc[mi][ni][q] = 0.f; tot[mi][ni][q] = 0.f; }

    auto load_stage = [&](int ch) {
        const int st = ch & 1;
        const int k0 = ch << 4;
        const uint32_t sb = sbase + st * STAGE_BYTES;
#pragma unroll
        for (int t = 0; t < 3; t++) {
            int idx = tid + (t << 8);
            int s = idx >> 8;
            int rem = idx & 255;
            int row = rem >> 1, half = rem & 1;
            const __nv_bfloat16* src =
                g_wsp + (size_t)s * WPL + (size_t)(mBase + row) * KTOT + k0 + half * 8;
            uint32_t d = sb + s * TILE_B + row * 48 + half * 16;
            cp16(d, src, 16);
        }
        {
            int tap = k0 >> 9;
            int coff = k0 & 511;
            int dy = tap / 3 - 1;
            int dx = tap - (tap / 3) * 3 - 1;
#pragma unroll
            for (int t = 0; t < 3; t++) {
                int idx = tid + (t << 8);
                int s = idx >> 8;
                int rem = idx & 255;
                int row = rem >> 1, half = rem & 1;
                int n = nBase + row;
                int nn = (n < PIX) ? n : 0;
                int y = nn / 50, x = nn - y * 50;
                int yy = y + dy, xx = x + dx;
                bool valid = (n < PIX) && ((unsigned)yy < 50u) && ((unsigned)xx < 50u);
                const __nv_bfloat16* src =
                    g_xsp + (size_t)s * XPL +
                    ((size_t)b * PIX + (valid ? (yy * 50 + xx) : 0)) * CIN + coff + half * 8;
                uint32_t d = sb + (3 + s) * TILE_B + row * 48 + half * 16;
                cp16(d, src, valid ? 16 : 0);
            }
        }
        CP_COMMIT();
    };

    load_stage(0);

    for (int ch = 0; ch < NCH; ch++) {
        if (ch + 1 < NCH) {
            load_stage(ch + 1);
            CP_WAIT1();
        } else {
            CP_WAIT0();
        }
        __syncthreads();

        const char* Sb = smc + (ch & 1) * STAGE_BYTES;

        uint32_t bfrag[3][4][2];
#pragma unroll
        for (int s = 0; s < 3; s++)
#pragma unroll
            for (int ni = 0; ni < 4; ni++) {
                const char* tb = Sb + (3 + s) * TILE_B + (wn + ni * 8 + lr) * 48 + lc * 4;
                bfrag[s][ni][0] = *reinterpret_cast<const uint32_t*>(tb);
                bfrag[s][ni][1] = *reinterpret_cast<const uint32_t*>(tb + 16);
            }

#pragma unroll
        for (int mi = 0; mi < 4; mi++) {
            uint32_t afrag[3][4];
#pragma unroll
            for (int s = 0; s < 3; s++) {
                const char* ta = Sb + s * TILE_B + (wm + mi * 16 + lr) * 48 + lc * 4;
                afrag[s][0] = *reinterpret_cast<const uint32_t*>(ta);
                afrag[s][1] = *reinterpret_cast<const uint32_t*>(ta + 8 * 48);
                afrag[s][2] = *reinterpret_cast<const uint32_t*>(ta + 16);
                afrag[s][3] = *reinterpret_cast<const uint32_t*>(ta + 8 * 48 + 16);
            }
#pragma unroll
            for (int ni = 0; ni < 4; ni++) {
                mma_bf16(acc[mi][ni], afrag[0], bfrag[0][ni]);   // a0 b0
                mma_bf16(acc[mi][ni], afrag[0], bfrag[1][ni]);   // a0 b1
                mma_bf16(acc[mi][ni], afrag[1], bfrag[0][ni]);   // a1 b0
                mma_bf16(acc[mi][ni], afrag[0], bfrag[2][ni]);   // a0 b2
                mma_bf16(acc[mi][ni], afrag[1], bfrag[1][ni]);   // a1 b1
                mma_bf16(acc[mi][ni], afrag[2], bfrag[0][ni]);   // a2 b0
            }
        }

        // ---- segmented accumulation: fold chunk into total, reset chunk acc ----
#pragma unroll
        for (int mi = 0; mi < 4; mi++)
#pragma unroll
            for (int ni = 0; ni < 4; ni++)
#pragma unroll
                for (int q = 0; q < 4; q++) {
                    tot[mi][ni][q] += acc[mi][ni][q];
                    acc[mi][ni][q] = 0.f;
                }
        __syncthreads();
    }

    // ---- epilogue: bias + relu -> g_h ----
#pragma unroll
    for (int mi = 0; mi < 4; mi++) {
        int m0 = mBase + wm + mi * 16 + lr;
        float bv0 = b1[m0];
        float bv8 = b1[m0 + 8];
        float* d0 = &g_h[((size_t)b * MIDC + m0) * PIX];
        float* d8 = &g_h[((size_t)b * MIDC + m0 + 8) * PIX];
#pragma unroll
        for (int ni = 0; ni < 4; ni++) {
            int n0 = nBase + wn + ni * 8 + 2 * lc;
            if (n0 < PIX) {
                float2 v0, v1;
                v0.x = fmaxf(tot[mi][ni][0] + bv0, 0.f);
                v0.y = fmaxf(tot[mi][ni][1] + bv0, 0.f);
                v1.x = fmaxf(tot[mi][ni][2] + bv8, 0.f);
                v1.y = fmaxf(tot[mi][ni][3] + bv8, 0.f);
                *reinterpret_cast<float2*>(&d0[n0]) = v0;
                *reinterpret_cast<float2*>(&d8[n0]) = v1;
            }
        }
    }
}

// ---------------- packed f32x2 helpers ----------------
__device__ __forceinline__ void fma2(unsigned long long& acc, unsigned long long a,
                                     unsigned long long b) {
    asm("fma.rn.f32x2 %0, %1, %2, %0;" : "+l"(acc) : "l"(a), "l"(b));
}
__device__ __forceinline__ unsigned long long dup2(float v) {
    unsigned long long d;
    asm("mov.b64 %0, {%1, %1};" : "=l"(d) : "f"(v));
    return d;
}
__device__ __forceinline__ float lo32(unsigned long long u) {
    return __uint_as_float((unsigned int)(u & 0xffffffffull));
}
__device__ __forceinline__ float hi32(unsigned long long u) {
    return __uint_as_float((unsigned int)(u >> 32));
}

// ================= Kernel 2: 1x1 heads (FFMA2) =================
__global__ __launch_bounds__(128) void heads_kernel(const float* __restrict__ Wl,
                                                    const float* __restrict__ bl,
                                                    const float* __restrict__ Ws,
                                                    const float* __restrict__ bs,
                                                    float* __restrict__ out) {
    __shared__ float wsh[64 * 56];
    __shared__ float bsm[54];

    const int b = blockIdx.y;
    const int p = blockIdx.x * 128 + threadIdx.x;
    const int tid = threadIdx.x;

    if (tid < 36) bsm[tid] = bl[tid];
    else if (tid < 54) bsm[tid] = bs[tid - 36];

    unsigned long long acc2[28];
#pragma unroll
    for (int q = 0; q < 28; q++) acc2[q] = 0ull;

    const float* hb = g_h + (size_t)(b * MIDC) * PIX;

    for (int c0 = 0; c0 < MIDC; c0 += 64) {
        __syncthreads();
        for (int idx = tid; idx < 64 * 56; idx += 128) {
            int cc = idx / 56, oc = idx - cc * 56;
            int c = c0 + cc;
            float v = 0.f;
            if (oc < 36) v = Wl[oc * MIDC + c];
            else if (oc < 54) v = Ws[(oc - 36) * MIDC + c];
            wsh[idx] = v;
        }
        __syncthreads();
        if (p < PIX) {
#pragma unroll 4
            for (int cc = 0; cc < 64; cc++) {
                float hv = __ldg(&hb[(size_t)(c0 + cc) * PIX + p]);
                unsigned long long hd = dup2(hv);
                const ulonglong2* wrow = reinterpret_cast<const ulonglong2*>(&wsh[cc * 56]);
#pragma unroll
                for (int q = 0; q < 14; q++) {
                    ulonglong2 wp = wrow[q];
                    fma2(acc2[q * 2 + 0], hd, wp.x);
                    fma2(acc2[q * 2 + 1], hd, wp.y);
                }
            }
        }
    }

    if (p < PIX) {
#pragma unroll
        for (int oc = 0; oc < 54; oc++) {
            unsigned long long u = acc2[oc >> 1];
            float v = ((oc & 1) ? hi32(u) : lo32(u)) + bsm[oc];
            if (oc < 36) {
                int a = oc >> 2, d = oc & 3;
                out[LOCS_OFF + ((size_t)b * NANCH + p * AA + a) * 4 + d] = v;
            } else {
                int o = oc - 36;
                int a = o >> 1, cc2 = o & 1;
                out[SCORES_OFF + ((size_t)b * NANCH + p * AA + a) * 2 + cc2] = v;
            }
        }
    }
}

// ================= Kernel 3: per-anchor prep =================
__global__ void prep_kernel(const float* __restrict__ out) {
    int idx = blockIdx.x * blockDim.x + threadIdx.x;
    if (idx >= BB * NANCH) return;
    int i = idx % NANCH;

    float s0 = out[SCORES_OFF + (size_t)idx * 2 + 0];
    float s1 = out[SCORES_OFF + (size_t)idx * 2 + 1];
    float m  = fmaxf(s0, s1);
    float e0 = expf(s0 - m), e1 = expf(s1 - m);
    float fg = e1 / (e0 + e1);

    int p  = i / AA, a = i - (i / AA) * AA;
    int iy = p / 50, ix = p - iy * 50;
    const double ratios[3] = {0.5, 1.0, 2.0};
    const double scales[3] = {8.0, 16.0, 32.0};
    int ri = a / 3;
    double r  = ratios[ri];
    double sc = scales[a - ri * 3];
    double hhd = 16.0 * sc * sqrt(r);
    double wwd = 16.0 * sc * sqrt(1.0 / r);
    float y1b = (float)(8.0 - hhd * 0.5);
    float x1b = (float)(8.0 - wwd * 0.5);
    float y2b = (float)(8.0 + hhd * 0.5);
    float x2b = (float)(8.0 + wwd * 0.5);
    float sy = (float)(iy * 16), sx = (float)(ix * 16);
    float ay1 = sy + y1b, ax1 = sx + x1b, ay2 = sy + y2b, ax2 = sx + x2b;

    float ha = ay2 - ay1, wa = ax2 - ax1;
    float cy = ay1 + 0.5f * ha, cx = ax1 + 0.5f * wa;

    const float* lp = out + LOCS_OFF + (size_t)idx * 4;
    float dy = lp[0], dx = lp[1], dh = lp[2], dw = lp[3];
    float ncy = dy * ha + cy;
    float ncx = dx * wa + cx;
    float nh = expf(dh) * ha;
    float nw = expf(dw) * wa;

    float y1 = fminf(fmaxf(ncy - 0.5f * nh, 0.f), IMGSZ);
    float x1 = fminf(fmaxf(ncx - 0.5f * nw, 0.f), IMGSZ);
    float y2 = fminf(fmaxf(ncy + 0.5f * nh, 0.f), IMGSZ);
    float x2 = fminf(fmaxf(ncx + 0.5f * nw, 0.f), IMGSZ);

    *reinterpret_cast<float4*>(&g_boxes[(size_t)idx * 4]) = make_float4(y1, x1, y2, x2);
    float hs = y2 - y1, ws2 = x2 - x1;
    g_s[idx] = (hs >= MINSZ && ws2 >= MINSZ) ? fg : -INFINITY;
}

// ================= Kernel 4: per-batch propose =================
__device__ __forceinline__ unsigned long long make_key(float s, int i) {
    unsigned int u = __float_as_uint(s);
    u = (u & 0x80000000u) ? ~u : (u | 0x80000000u);
    unsigned int inv = ~u;
    return (((unsigned long long)inv) << 32) | (unsigned int)i;
}

#define OFF_KEYS 19200
#define OFF_HIST 35584
#define OFF_MASK 19200
#define DYN_SMEM 201600

__global__ __launch_bounds__(1024) void propose_kernel(float* __restrict__ out) {
    extern __shared__ unsigned char dyn[];
    float4* sboxes = reinterpret_cast<float4*>(dyn);
    unsigned long long* keys = reinterpret_cast<unsigned long long*>(dyn + OFF_KEYS);
    unsigned int* hist = reinterpret_cast<unsigned int*>(dyn + OFF_HIST);
    unsigned int* umask = reinterpret_cast<unsigned int*>(dyn + OFF_MASK);

    __shared__ unsigned long long sh_prefix;
    __shared__ int sh_rem, sh_cnt, sh_done;
    __shared__ unsigned int keepw[NWORDS];
    __shared__ unsigned int kpre[NWORDS + 1];

    const int b = blockIdx.x;
    const int tid = threadIdx.x;
    const int lane = tid & 31;
    const int wid = tid >> 5;
    const float* sb = g_s + (size_t)b * NANCH;

    unsigned long long prefix = 0ull;
    int pb = 0;
    int remaining = NPRE - 1;
    const int widths[6] = {11, 11, 11, 11, 11, 9};
    if (tid == 0) sh_done = 0;
    __syncthreads();
    for (int pass = 0; pass < 6; pass++) {
        int w  = widths[pass];
        int nbk = 1 << w;
        for (int t = tid; t < 2048; t += 1024) hist[t] = 0;
        __syncthreads();
        int shift = 64 - pb - w;
        for (int i0 = tid; i0 < 23552; i0 += 1024) {
            bool valid = (i0 < NANCH);
            unsigned int d = 0;
            if (valid) {
                unsigned long long key = make_key(sb[i0], i0);
                valid = (pb == 0) || ((key >> (64 - pb)) == prefix);
                d = (unsigned int)((key >> shift) & (unsigned long long)(nbk - 1));
            }
            unsigned int am = __ballot_sync(0xffffffffu, valid);
            if (valid) {
                unsigned int mm = __match_any_sync(am, d);
                if ((__ffs(mm) - 1) == lane) atomicAdd(&hist[d], (unsigned int)__popc(mm));
            }
        }
        __syncthreads();
        if (tid == 0) {
            unsigned int cum = 0;
            for (int d = 0; d < nbk; d++) {
                unsigned int c = hist[d];
                if (cum + c > (unsigned int)remaining) {
                    sh_prefix = (prefix << w) | (unsigned long long)d;
                    sh_rem = remaining - (int)cum;
                    int count_less = (NPRE - 1) - (remaining - (int)cum);
                    if (count_less + (int)c <= 2048) sh_done = 1;
                    break;
                }
                cum += c;
            }
        }
        __syncthreads();
        prefix = sh_prefix;
        remaining = sh_rem;
        pb += w;
        if (sh_done) break;
        __syncthreads();
    }

    if (tid == 0) sh_cnt = 0;
    __syncthreads();
    {
        int s = 64 - pb;
        for (int i0 = tid; i0 < 23552; i0 += 1024) {
            bool pred = false;
            unsigned long long key = 0;
            if (i0 < NANCH) {
                key = make_key(sb[i0], i0);
                pred = ((key >> s) <= prefix);
            }
            unsigned int bal = __ballot_sync(0xffffffffu, pred);
            int nset = __popc(bal);
            if (nset) {
                int basep = 0;
                int leader = __ffs(bal) - 1;
                if (lane == leader) basep = atomicAdd(&sh_cnt, nset);
                basep = __shfl_sync(0xffffffffu, basep, leader);
                if (pred) {
                    int pos = basep + __popc(bal & ((1u << lane) - 1u));
                    if (pos < 2048) keys[pos] = key;
                }
            }
        }
    }
    __syncthreads();
    int cnt = sh_cnt;
    if (cnt > 2048) cnt = 2048;
    for (int t = tid; t < 2048; t += 1024)
        if (t >= cnt) keys[t] = 0xFFFFFFFFFFFFFFFFull;
    __syncthreads();

    for (int k = 2; k <= 2048; k <<= 1) {
        for (int j = k >> 1; j > 0; j >>= 1) {
            for (int t = tid; t < 2048; t += 1024) {
                int ixj = t ^ j;
                if (ixj > t) {
                    unsigned long long va = keys[t], vb = keys[ixj];
                    bool up = ((t & k) == 0);
                    if ((va > vb) == up) { keys[t] = vb; keys[ixj] = va; }
                }
            }
            __syncthreads();
        }
    }

    for (int t = tid; t < NPRE; t += 1024) {
        int idx = (int)(unsigned int)(keys[t] & 0xFFFFFFFFull);
        sboxes[t] = *reinterpret_cast<const float4*>(&g_boxes[((size_t)b * NANCH + idx) * 4]);
    }
    __syncthreads();

    for (int i = wid; i < NPRE; i += 32) {
        float4 bi = sboxes[i];
        float areai = (bi.z - bi.x) * (bi.w - bi.y);
        int w0 = i >> 5;
        for (int w = w0; w < NWORDS; w++) {
            int j = (w << 5) + lane;
            unsigned int pred = 0;
            if (j > i && j < NPRE) {
                float4 bj = sboxes[j];
                float iy  = fmaxf(fminf(bi.z, bj.z) - fmaxf(bi.x, bj.x), 0.f);
                float ixl = fmaxf(fminf(bi.w, bj.w) - fmaxf(bi.y, bj.y), 0.f);
                float inter = iy * ixl;
                float areaj = (bj.z - bj.x) * (bj.w - bj.y);
                float iou = inter / (areai + areaj - inter + 1e-9f);
                pred = (iou > NMS_THRESH) ? 1u : 0u;
            }
            unsigned int word = __ballot_sync(0xffffffffu, pred);
            if (lane == 0) umask[i * NWORDS + w] = word;
        }
    }
    __syncthreads();

    if (wid == 0) {
        unsigned int sup0 = 0, sup1 = 0;
        unsigned int kb0 = 0, kb1 = 0;
        for (int i = 0; i < NPRE; i++) {
            int w = i >> 5, bit = i & 31;
            unsigned int v = (w < 32) ? sup0 : sup1;
            int src = (w < 32) ? w : (w - 32);
            unsigned int word = __shfl_sync(0xffffffffu, v, src);
            if (!((word >> bit) & 1u)) {
                if (lane == src) { if (w < 32) kb0 |= (1u << bit); else kb1 |= (1u << bit); }
                sup0 |= umask[i * NWORDS + lane];
                if (lane < NWORDS - 32) sup1 |= umask[i * NWORDS + 32 + lane];
            }
        }
        keepw[lane] = kb0;
        if (lane < NWORDS - 32) keepw[32 + lane] = kb1;
    }
    __syncthreads();

    if (tid == 0) {
        unsigned int s = 0;
        for (int w = 0; w < NWORDS; w++) { kpre[w] = s; s += __popc(keepw[w]); }
        kpre[NWORDS] = s;
    }
    __syncthreads();

    int nkept = kpre[NWORDS];
    for (int t = tid; t < NPRE; t += 1024) {
        int w = t >> 5, bit = t & 31;
        bool kp = (keepw[w] >> bit) & 1u;
        int keptBefore = kpre[w] + __popc(keepw[w] & ((1u << bit) - 1u));
        int rank = kp ? keptBefore : nkept + (t - keptBefore);
        if (rank < NPOST) {
            float4 bx = sboxes[t];
            *reinterpret_cast<float4*>(&out[ROIS_OFF + ((size_t)b * NPOST + rank) * 4]) = bx;
        }
    }
}

// ================= launch =================
extern "C" void kernel_launch(void* const* d_in, const int* in_sizes, int n_in,
                              void* d_out, int out_size) {
    const float* x  = (const float*)d_in[0];
    const float* W1 = (const float*)d_in[1];
    const float* b1 = (const float*)d_in[2];
    const float* Wl = (const float*)d_in[3];
    const float* bl = (const float*)d_in[4];
    const float* Ws = (const float*)d_in[5];
    const float* bs = (const float*)d_in[6];
    float* out = (float*)d_out;

    prep_w<<<(WPL + 255) / 256, 256>>>(W1);
    dim3 gx((PIX + 31) / 32, CIN / 32, BB);
    prep_x<<<gx, dim3(32, 8)>>>(x);

    cudaFuncSetAttribute(conv_mma, cudaFuncAttributeMaxDynamicSharedMemorySize, CONV_SMEM);
    conv_mma<<<dim3(20, 4, BB), 256, CONV_SMEM>>>(b1);

    dim3 gheads((PIX + 127) / 128, BB);
    heads_kernel<<<gheads, 128>>>(Wl, bl, Ws, bs, out);

    int tot2 = BB * NANCH;
    prep_kernel<<<(tot2 + 255) / 256, 256>>>(out);

    cudaFuncSetAttribute(propose_kernel, cudaFuncAttributeMaxDynamicSharedMemorySize, DYN_SMEM);
    propose_kernel<<<BB, 1024, DYN_SMEM>>>(out);
}

// round 8
// speedup vs baseline: 2.1485x; 1.5634x over previous
#include <cuda_runtime.h>
#include <cuda_fp16.h>
#include <math.h>
#include <cstdint>

// ---------------- problem constants ----------------
#define BB 4
#define CIN 512
#define MIDC 512
#define PIX 2500
#define KTOT 4608
#define AA 9
#define NANCH 22500
#define NPRE 1200
#define NPOST 300
#define IMGSZ 800.0f
#define NMS_THRESH 0.7f
#define MINSZ 16.0f

#define LOCS_OFF   0
#define SCORES_OFF 360000
#define ROIS_OFF   540000

#define NWORDS 38

// conv mma tiling (fp16 x3, weight prescale 2^10)
#define NCH 288             // 4608/16
#define TILE_B 6144         // 128 rows x 48B (32B fp16 data + 16 pad)
#define STAGE_BYTES 24576   // 4 tiles: a0,a1,b0,b1
#define CONV_SMEM (2 * STAGE_BYTES)
#define WSCALE 1024.0f
#define WUNSCALE 0.0009765625f

#define WPL (MIDC * KTOT)
#define XPL (BB * PIX * CIN)

// ---------------- scratch ----------------
__device__ float g_h[BB * MIDC * PIX];
__device__ float g_s[BB * NANCH];
__device__ float g_boxes[BB * NANCH * 4];
__device__ __half g_wh[2 * WPL];            // scaled weight splits
__device__ __half g_xh[2 * XPL];            // x splits
__device__ float g_hp[16 * 56 * PIX];       // heads partials [slice*4+b][56][p]
__device__ float g_sorted[BB * NPRE * 4];   // sorted top-1200 boxes
__device__ unsigned int g_masku[BB * NPRE * NWORDS];

// ---------------- helpers ----------------
__device__ __forceinline__ uint32_t smem_u32(const void* p) {
    uint32_t a;
    asm("{ .reg .u64 t; cvta.to.shared.u64 t, %1; cvt.u32.u64 %0, t; }" : "=r"(a) : "l"(p));
    return a;
}
__device__ __forceinline__ void cp16(uint32_t dst, const void* src, int sz) {
    asm volatile("cp.async.ca.shared.global [%0], [%1], 16, %2;"
                 :: "r"(dst), "l"(src), "r"(sz) : "memory");
}
#define CP_COMMIT() asm volatile("cp.async.commit_group;" ::: "memory")
#define CP_WAIT1()  asm volatile("cp.async.wait_group 1;" ::: "memory")
#define CP_WAIT0()  asm volatile("cp.async.wait_group 0;" ::: "memory")

__device__ __forceinline__ void mma_f16(float* d, const uint32_t* a, const uint32_t* bf) {
    asm volatile(
        "mma.sync.aligned.m16n8k16.row.col.f32.f16.f16.f32 "
        "{%0,%1,%2,%3}, {%4,%5,%6,%7}, {%8,%9}, {%0,%1,%2,%3};"
        : "+f"(d[0]), "+f"(d[1]), "+f"(d[2]), "+f"(d[3])
        : "r"(a[0]), "r"(a[1]), "r"(a[2]), "r"(a[3]), "r"(bf[0]), "r"(bf[1]));
}

__device__ __forceinline__ void f16_split2(float v, __half& s0, __half& s1) {
    __half h0 = __float2half_rn(v);
    float r = v - __half2float(h0);
    s0 = h0;
    s1 = __float2half_rn(r);
}

// ================= prep: weight reorder + scale + fp16 2-split =================
__global__ void prep_w(const float* __restrict__ W1) {
    int idx = blockIdx.x * 256 + threadIdx.x;
    if (idx >= WPL) return;
    int oc = idx / KTOT, kn = idx - oc * KTOT;
    int r = kn >> 9, c = kn & 511;
    float v = W1[(size_t)oc * KTOT + c * 9 + r] * WSCALE;
    __half s0, s1;
    f16_split2(v, s0, s1);
    g_wh[idx] = s0;
    g_wh[WPL + idx] = s1;
}

// ================= prep: X NCHW -> NHWC + fp16 2-split =================
__global__ void prep_x(const float* __restrict__ X) {
    __shared__ float t[32][33];
    int b = blockIdx.z;
    int p0 = blockIdx.x * 32;
    int c0 = blockIdx.y * 32;
    int tx = threadIdx.x, ty = threadIdx.y;
    const float* Xb = X + ((size_t)b * CIN + c0) * PIX;
#pragma unroll
    for (int k = 0; k < 32; k += 8) {
        int p = p0 + tx;
        t[ty + k][tx] = (p < PIX) ? Xb[(size_t)(ty + k) * PIX + p] : 0.f;
    }
    __syncthreads();
#pragma unroll
    for (int k = 0; k < 32; k += 8) {
        int p = p0 + ty + k;
        if (p < PIX) {
            float v = t[tx][ty + k];
            __half s0, s1;
            f16_split2(v, s0, s1);
            size_t o = ((size_t)b * PIX + p) * CIN + c0 + tx;
            g_xh[o] = s0;
            g_xh[XPL + o] = s1;
        }
    }
}

// ================= Kernel 1: conv3x3+relu, FP16x3 MMA + segmented accumulation ========
__global__ __launch_bounds__(256) void conv_mma(const float* __restrict__ b1) {
    extern __shared__ char smc[];

    const int b = blockIdx.z;
    const int mBase = blockIdx.y * 128;
    const int nBase = blockIdx.x * 128;
    const int tid = threadIdx.x;
    const int wid = tid >> 5;
    const int lane = tid & 31;
    const int lr = lane >> 2;
    const int lc = lane & 3;

    const int wm = (wid & 1) * 64;
    const int wn = (wid >> 1) * 32;

    const uint32_t sbase = smem_u32(smc);

    float acc[4][4][4];
    float tot[4][4][4];
#pragma unroll
    for (int mi = 0; mi < 4; mi++)
#pragma unroll
        for (int ni = 0; ni < 4; ni++)
#pragma unroll
            for (int q = 0; q < 4; q++) { acc[mi][ni][q] = 0.f; tot[mi][ni][q] = 0.f; }

    auto load_stage = [&](int ch) {
        const int st = ch & 1;
        const int k0 = ch << 4;
        const uint32_t sb = sbase + st * STAGE_BYTES;
        // A: 2 splits x 128 rows x 2 halves = 512 cp ops
#pragma unroll
        for (int t = 0; t < 2; t++) {
            int idx = tid + (t << 8);
            int s = idx >> 8;
            int rem = idx & 255;
            int row = rem >> 1, half = rem & 1;
            const __half* src =
                g_wh + (size_t)s * WPL + (size_t)(mBase + row) * KTOT + k0 + half * 8;
            uint32_t d = sb + s * TILE_B + row * 48 + half * 16;
            cp16(d, src, 16);
        }
        // B: 2 splits x 128 rows x 2 halves
        {
            int tap = k0 >> 9;
            int coff = k0 & 511;
            int dy = tap / 3 - 1;
            int dx = tap - (tap / 3) * 3 - 1;
#pragma unroll
            for (int t = 0; t < 2; t++) {
                int idx = tid + (t << 8);
                int s = idx >> 8;
                int rem = idx & 255;
                int row = rem >> 1, half = rem & 1;
                int n = nBase + row;
                int nn = (n < PIX) ? n : 0;
                int y = nn / 50, x = nn - y * 50;
                int yy = y + dy, xx = x + dx;
                bool valid = (n < PIX) && ((unsigned)yy < 50u) && ((unsigned)xx < 50u);
                const __half* src =
                    g_xh + (size_t)s * XPL +
                    ((size_t)b * PIX + (valid ? (yy * 50 + xx) : 0)) * CIN + coff + half * 8;
                uint32_t d = sb + (2 + s) * TILE_B + row * 48 + half * 16;
                cp16(d, src, valid ? 16 : 0);
            }
        }
        CP_COMMIT();
    };

    load_stage(0);

    for (int ch = 0; ch < NCH; ch++) {
        if (ch + 1 < NCH) {
            load_stage(ch + 1);
            CP_WAIT1();
        } else {
            CP_WAIT0();
        }
        __syncthreads();

        const char* Sb = smc + (ch & 1) * STAGE_BYTES;

        uint32_t bfrag[2][4][2];
#pragma unroll
        for (int s = 0; s < 2; s++)
#pragma unroll
            for (int ni = 0; ni < 4; ni++) {
                const char* tb = Sb + (2 + s) * TILE_B + (wn + ni * 8 + lr) * 48 + lc * 4;
                bfrag[s][ni][0] = *reinterpret_cast<const uint32_t*>(tb);
                bfrag[s][ni][1] = *reinterpret_cast<const uint32_t*>(tb + 16);
            }

#pragma unroll
        for (int mi = 0; mi < 4; mi++) {
            uint32_t afrag[2][4];
#pragma unroll
            for (int s = 0; s < 2; s++) {
                const char* ta = Sb + s * TILE_B + (wm + mi * 16 + lr) * 48 + lc * 4;
                afrag[s][0] = *reinterpret_cast<const uint32_t*>(ta);
                afrag[s][1] = *reinterpret_cast<const uint32_t*>(ta + 8 * 48);
                afrag[s][2] = *reinterpret_cast<const uint32_t*>(ta + 16);
                afrag[s][3] = *reinterpret_cast<const uint32_t*>(ta + 8 * 48 + 16);
            }
#pragma unroll
            for (int ni = 0; ni < 4; ni++) {
                mma_f16(acc[mi][ni], afrag[0], bfrag[0][ni]);   // a0 b0
                mma_f16(acc[mi][ni], afrag[1], bfrag[0][ni]);   // a1 b0
                mma_f16(acc[mi][ni], afrag[0], bfrag[1][ni]);   // a0 b1
            }
        }

        // ---- fold every 2 chunks (K=32 segments) ----
        if (ch & 1) {
#pragma unroll
            for (int mi = 0; mi < 4; mi++)
#pragma unroll
                for (int ni = 0; ni < 4; ni++)
#pragma unroll
                    for (int q = 0; q < 4; q++) {
                        tot[mi][ni][q] += acc[mi][ni][q];
                        acc[mi][ni][q] = 0.f;
                    }
        }
        __syncthreads();
    }

    // ---- epilogue: unscale + bias + relu -> g_h ----
#pragma unroll
    for (int mi = 0; mi < 4; mi++) {
        int m0 = mBase + wm + mi * 16 + lr;
        float bv0 = b1[m0];
        float bv8 = b1[m0 + 8];
        float* d0 = &g_h[((size_t)b * MIDC + m0) * PIX];
        float* d8 = &g_h[((size_t)b * MIDC + m0 + 8) * PIX];
#pragma unroll
        for (int ni = 0; ni < 4; ni++) {
            int n0 = nBase + wn + ni * 8 + 2 * lc;
            if (n0 < PIX) {
                float2 v0, v1;
                v0.x = fmaxf(fmaf(tot[mi][ni][0], WUNSCALE, bv0), 0.f);
                v0.y = fmaxf(fmaf(tot[mi][ni][1], WUNSCALE, bv0), 0.f);
                v1.x = fmaxf(fmaf(tot[mi][ni][2], WUNSCALE, bv8), 0.f);
                v1.y = fmaxf(fmaf(tot[mi][ni][3], WUNSCALE, bv8), 0.f);
                *reinterpret_cast<float2*>(&d0[n0]) = v0;
                *reinterpret_cast<float2*>(&d8[n0]) = v1;
            }
        }
    }
}

// ---------------- packed f32x2 helpers ----------------
__device__ __forceinline__ void fma2(unsigned long long& acc, unsigned long long a,
                                     unsigned long long b) {
    asm("fma.rn.f32x2 %0, %1, %2, %0;" : "+l"(acc) : "l"(a), "l"(b));
}
__device__ __forceinline__ unsigned long long dup2(float v) {
    unsigned long long d;
    asm("mov.b64 %0, {%1, %1};" : "=l"(d) : "f"(v));
    return d;
}
__device__ __forceinline__ float lo32(unsigned long long u) {
    return __uint_as_float((unsigned int)(u & 0xffffffffull));
}
__device__ __forceinline__ float hi32(unsigned long long u) {
    return __uint_as_float((unsigned int)(u >> 32));
}

// ================= Kernel 2a: heads partial (split-K x4) =================
__global__ __launch_bounds__(128) void heads_part(const float* __restrict__ Wl,
                                                  const float* __restrict__ Ws) {
    __shared__ float wsh[64 * 56];

    const int b = blockIdx.z;
    const int slice = blockIdx.y;
    const int p = blockIdx.x * 128 + threadIdx.x;
    const int tid = threadIdx.x;

    unsigned long long acc2[28];
#pragma unroll
    for (int q = 0; q < 28; q++) acc2[q] = 0ull;

    const float* hb = g_h + (size_t)(b * MIDC) * PIX;
    const int cbase = slice * 128;

    for (int c0 = cbase; c0 < cbase + 128; c0 += 64) {
        __syncthreads();
        for (int idx = tid; idx < 64 * 56; idx += 128) {
            int cc = idx / 56, oc = idx - cc * 56;
            int c = c0 + cc;
            float v = 0.f;
            if (oc < 36) v = Wl[oc * MIDC + c];
            else if (oc < 54) v = Ws[(oc - 36) * MIDC + c];
            wsh[idx] = v;
        }
        __syncthreads();
        if (p < PIX) {
#pragma unroll 4
            for (int cc = 0; cc < 64; cc++) {
                float hv = __ldg(&hb[(size_t)(c0 + cc) * PIX + p]);
                unsigned long long hd = dup2(hv);
                const ulonglong2* wrow = reinterpret_cast<const ulonglong2*>(&wsh[cc * 56]);
#pragma unroll
                for (int q = 0; q < 14; q++) {
                    ulonglong2 wp = wrow[q];
                    fma2(acc2[q * 2 + 0], hd, wp.x);
                    fma2(acc2[q * 2 + 1], hd, wp.y);
                }
            }
        }
    }

    if (p < PIX) {
        float* dst = &g_hp[((size_t)(slice * BB + b) * 56) * PIX + p];
#pragma unroll
        for (int oc = 0; oc < 54; oc++) {
            unsigned long long u = acc2[oc >> 1];
            float v = (oc & 1) ? hi32(u) : lo32(u);
            dst[(size_t)oc * PIX] = v;
        }
    }
}

// ================= Kernel 2b: heads combine (fixed order, deterministic) =============
__global__ __launch_bounds__(128) void heads_comb(const float* __restrict__ bl,
                                                  const float* __restrict__ bs,
                                                  float* __restrict__ out) {
    int idx = blockIdx.x * 128 + threadIdx.x;
    if (idx >= BB * PIX) return;
    int b = idx / PIX, p = idx - b * PIX;

#pragma unroll 6
    for (int oc = 0; oc < 54; oc++) {
        float v = (oc < 36) ? __ldg(&bl[oc]) : __ldg(&bs[oc - 36]);
        float s0 = g_hp[((size_t)(0 * BB + b) * 56 + oc) * PIX + p];
        float s1 = g_hp[((size_t)(1 * BB + b) * 56 + oc) * PIX + p];
        float s2 = g_hp[((size_t)(2 * BB + b) * 56 + oc) * PIX + p];
        float s3 = g_hp[((size_t)(3 * BB + b) * 56 + oc) * PIX + p];
        v = v + s0 + s1 + s2 + s3;
        if (oc < 36) {
            int a = oc >> 2, d = oc & 3;
            out[LOCS_OFF + ((size_t)b * NANCH + p * AA + a) * 4 + d] = v;
        } else {
            int o = oc - 36;
            int a = o >> 1, cc2 = o & 1;
            out[SCORES_OFF + ((size_t)b * NANCH + p * AA + a) * 2 + cc2] = v;
        }
    }
}

// ================= Kernel 3: per-anchor prep =================
__global__ void prep_kernel(const float* __restrict__ out) {
    int idx = blockIdx.x * blockDim.x + threadIdx.x;
    if (idx >= BB * NANCH) return;
    int i = idx % NANCH;

    float s0 = out[SCORES_OFF + (size_t)idx * 2 + 0];
    float s1 = out[SCORES_OFF + (size_t)idx * 2 + 1];
    float m  = fmaxf(s0, s1);
    float e0 = expf(s0 - m), e1 = expf(s1 - m);
    float fg = e1 / (e0 + e1);

    int p  = i / AA, a = i - (i / AA) * AA;
    int iy = p / 50, ix = p - iy * 50;
    const double ratios[3] = {0.5, 1.0, 2.0};
    const double scales[3] = {8.0, 16.0, 32.0};
    int ri = a / 3;
    double r  = ratios[ri];
    double sc = scales[a - ri * 3];
    double hhd = 16.0 * sc * sqrt(r);
    double wwd = 16.0 * sc * sqrt(1.0 / r);
    float y1b = (float)(8.0 - hhd * 0.5);
    float x1b = (float)(8.0 - wwd * 0.5);
    float y2b = (float)(8.0 + hhd * 0.5);
    float x2b = (float)(8.0 + wwd * 0.5);
    float sy = (float)(iy * 16), sx = (float)(ix * 16);
    float ay1 = sy + y1b, ax1 = sx + x1b, ay2 = sy + y2b, ax2 = sx + x2b;

    float ha = ay2 - ay1, wa = ax2 - ax1;
    float cy = ay1 + 0.5f * ha, cx = ax1 + 0.5f * wa;

    const float* lp = out + LOCS_OFF + (size_t)idx * 4;
    float dy = lp[0], dx = lp[1], dh = lp[2], dw = lp[3];
    float ncy = dy * ha + cy;
    float ncx = dx * wa + cx;
    float nh = expf(dh) * ha;
    float nw = expf(dw) * wa;

    float y1 = fminf(fmaxf(ncy - 0.5f * nh, 0.f), IMGSZ);
    float x1 = fminf(fmaxf(ncx - 0.5f * nw, 0.f), IMGSZ);
    float y2 = fminf(fmaxf(ncy + 0.5f * nh, 0.f), IMGSZ);
    float x2 = fminf(fmaxf(ncx + 0.5f * nw, 0.f), IMGSZ);

    *reinterpret_cast<float4*>(&g_boxes[(size_t)idx * 4]) = make_float4(y1, x1, y2, x2);
    float hs = y2 - y1, ws2 = x2 - x1;
    g_s[idx] = (hs >= MINSZ && ws2 >= MINSZ) ? fg : -INFINITY;
}

// ================= Kernel 4a: per-batch select + sort =================
__device__ __forceinline__ unsigned long long make_key(float s, int i) {
    unsigned int u = __float_as_uint(s);
    u = (u & 0x80000000u) ? ~u : (u | 0x80000000u);
    unsigned int inv = ~u;
    return (((unsigned long long)inv) << 32) | (unsigned int)i;
}

__global__ __launch_bounds__(1024) void propose_sort(void) {
    __shared__ unsigned long long keys[2048];
    __shared__ unsigned int hist[2048];
    __shared__ unsigned long long sh_prefix;
    __shared__ int sh_rem, sh_cnt, sh_done;

    const int b = blockIdx.x;
    const int tid = threadIdx.x;
    const int lane = tid & 31;
    const float* sb = g_s + (size_t)b * NANCH;

    unsigned long long prefix = 0ull;
    int pb = 0;
    int remaining = NPRE - 1;
    const int widths[6] = {11, 11, 11, 11, 11, 9};
    if (tid == 0) sh_done = 0;
    __syncthreads();
    for (int pass = 0; pass < 6; pass++) {
        int w  = widths[pass];
        int nbk = 1 << w;
        for (int t = tid; t < 2048; t += 1024) hist[t] = 0;
        __syncthreads();
        int shift = 64 - pb - w;
        for (int i0 = tid; i0 < 23552; i0 += 1024) {
            bool valid = (i0 < NANCH);
            unsigned int d = 0;
            if (valid) {
                unsigned long long key = make_key(sb[i0], i0);
                valid = (pb == 0) || ((key >> (64 - pb)) == prefix);
                d = (unsigned int)((key >> shift) & (unsigned long long)(nbk - 1));
            }
            unsigned int am = __ballot_sync(0xffffffffu, valid);
            if (valid) {
                unsigned int mm = __match_any_sync(am, d);
                if ((__ffs(mm) - 1) == lane) atomicAdd(&hist[d], (unsigned int)__popc(mm));
            }
        }
        __syncthreads();
        if (tid == 0) {
            unsigned int cum = 0;
            for (int d = 0; d < nbk; d++) {
                unsigned int c = hist[d];
                if (cum + c > (unsigned int)remaining) {
                    sh_prefix = (prefix << w) | (unsigned long long)d;
                    sh_rem = remaining - (int)cum;
                    int count_less = (NPRE - 1) - (remaining - (int)cum);
                    if (count_less + (int)c <= 2048) sh_done = 1;
                    break;
                }
                cum += c;
            }
        }
        __syncthreads();
        prefix = sh_prefix;
        remaining = sh_rem;
        pb += w;
        if (sh_done) break;
        __syncthreads();
    }

    if (tid == 0) sh_cnt = 0;
    __syncthreads();
    {
        int s = 64 - pb;
        for (int i0 = tid; i0 < 23552; i0 += 1024) {
            bool pred = false;
            unsigned long long key = 0;
            if (i0 < NANCH) {
                key = make_key(sb[i0], i0);
                pred = ((key >> s) <= prefix);
            }
            unsigned int bal = __ballot_sync(0xffffffffu, pred);
            int nset = __popc(bal);
            if (nset) {
                int basep = 0;
                int leader = __ffs(bal) - 1;
                if (lane == leader) basep = atomicAdd(&sh_cnt, nset);
                basep = __shfl_sync(0xffffffffu, basep, leader);
                if (pred) {
                    int pos = basep + __popc(bal & ((1u << lane) - 1u));
                    if (pos < 2048) keys[pos] = key;
                }
            }
        }
    }
    __syncthreads();
    int cnt = sh_cnt;
    if (cnt > 2048) cnt = 2048;
    for (int t = tid; t < 2048; t += 1024)
        if (t >= cnt) keys[t] = 0xFFFFFFFFFFFFFFFFull;
    __syncthreads();

    for (int k = 2; k <= 2048; k <<= 1) {
        for (int j = k >> 1; j > 0; j >>= 1) {
            for (int t = tid; t < 2048; t += 1024) {
                int ixj = t ^ j;
                if (ixj > t) {
                    unsigned long long va = keys[t], vb = keys[ixj];
                    bool up = ((t & k) == 0);
                    if ((va > vb) == up) { keys[t] = vb; keys[ixj] = va; }
                }
            }
            __syncthreads();
        }
    }

    // gather top-NPRE boxes to gmem
    for (int t = tid; t < NPRE; t += 1024) {
        int idx = (int)(unsigned int)(keys[t] & 0xFFFFFFFFull);
        float4 bx = *reinterpret_cast<const float4*>(&g_boxes[((size_t)b * NANCH + idx) * 4]);
        *reinterpret_cast<float4*>(&g_sorted[((size_t)b * NPRE + t) * 4]) = bx;
    }
}

// ================= Kernel 4b: IoU bitmask (parallel across SMs) =================
__global__ __launch_bounds__(128) void propose_mask(void) {
    __shared__ float4 sboxes[NPRE];
    const int b = blockIdx.y;
    const int tid = threadIdx.x;
    const int lane = tid & 31;
    const int warp = tid >> 5;

    for (int t = tid; t < NPRE; t += 128)
        sboxes[t] = *reinterpret_cast<const float4*>(&g_sorted[((size_t)b * NPRE + t) * 4]);
    __syncthreads();

    int i0 = blockIdx.x * 120 + warp * 30;
    for (int i = i0; i < i0 + 30; i++) {
        float4 bi = sboxes[i];
        float areai = (bi.z - bi.x) * (bi.w - bi.y);
        int w0 = i >> 5;
        for (int w = w0; w < NWORDS; w++) {
            int j = (w << 5) + lane;
            unsigned int pred = 0;
            if (j > i && j < NPRE) {
                float4 bj = sboxes[j];
                float iy  = fmaxf(fminf(bi.z, bj.z) - fmaxf(bi.x, bj.x), 0.f);
                float ixl = fmaxf(fminf(bi.w, bj.w) - fmaxf(bi.y, bj.y), 0.f);
                float inter = iy * ixl;
                float areaj = (bj.z - bj.x) * (bj.w - bj.y);
                // inter/(union+eps) > TH  <=>  inter > TH*(union+eps)
                pred = (inter > NMS_THRESH * (areai + areaj - inter + 1e-9f)) ? 1u : 0u;
            }
            unsigned int word = __ballot_sync(0xffffffffu, pred);
            if (lane == 0) g_masku[((size_t)b * NPRE + i) * NWORDS + w] = word;
        }
    }
}

// ================= Kernel 4c: greedy sweep + emit =================
#define SWEEP_SMEM (NPRE * NWORDS * 4)   // 182400

__global__ __launch_bounds__(1024) void propose_sweep(float* __restrict__ out) {
    extern __shared__ unsigned int msk[];
    __shared__ unsigned int keepw[NWORDS];
    __shared__ unsigned int kpre[NWORDS + 1];

    const int b = blockIdx.x;
    const int tid = threadIdx.x;
    const int lane = tid & 31;
    const int wid = tid >> 5;

    const unsigned int* gm = &g_masku[(size_t)b * NPRE * NWORDS];
    for (int t = tid; t < NPRE * NWORDS; t += 1024) msk[t] = gm[t];
    __syncthreads();

    if (wid == 0) {
        unsigned int sup0 = 0, sup1 = 0;
        unsigned int kb0 = 0, kb1 = 0;
#pragma unroll 4
        for (int i = 0; i < NPRE; i++) {
            int w = i >> 5, bit = i & 31;
            // unconditional prefetch of mask row (off the serial chain)
            unsigned int mrow  = msk[i * NWORDS + lane];
            unsigned int mrow2 = (lane < NWORDS - 32) ? msk[i * NWORDS + 32 + lane] : 0u;
            unsigned int v = (w < 32) ? sup0 : sup1;
            int src = (w < 32) ? w : (w - 32);
            unsigned int word = __shfl_sync(0xffffffffu, v, src);
            if (!((word >> bit) & 1u)) {
                if (lane == src) { if (w < 32) kb0 |= (1u << bit); else kb1 |= (1u << bit); }
                sup0 |= mrow;
                sup1 |= mrow2;
            }
        }
        keepw[lane] = kb0;
        if (lane < NWORDS - 32) keepw[32 + lane] = kb1;
    }
    __syncthreads();

    if (tid == 0) {
        unsigned int s = 0;
        for (int w = 0; w < NWORDS; w++) { kpre[w] = s; s += __popc(keepw[w]); }
        kpre[NWORDS] = s;
    }
    __syncthreads();

    int nkept = kpre[NWORDS];
    for (int t = tid; t < NPRE; t += 1024) {
        int w = t >> 5, bit = t & 31;
        bool kp = (keepw[w] >> bit) & 1u;
        int keptBefore = kpre[w] + __popc(keepw[w] & ((1u << bit) - 1u));
        int rank = kp ? keptBefore : nkept + (t - keptBefore);
        if (rank < NPOST) {
            float4 bx = *reinterpret_cast<const float4*>(&g_sorted[((size_t)b * NPRE + t) * 4]);
            *reinterpret_cast<float4*>(&out[ROIS_OFF + ((size_t)b * NPOST + rank) * 4]) = bx;
        }
    }
}

// ================= launch =================
extern "C" void kernel_launch(void* const* d_in, const int* in_sizes, int n_in,
                              void* d_out, int out_size) {
    const float* x  = (const float*)d_in[0];
    const float* W1 = (const float*)d_in[1];
    const float* b1 = (const float*)d_in[2];
    const float* Wl = (const float*)d_in[3];
    const float* bl = (const float*)d_in[4];
    const float* Ws = (const float*)d_in[5];
    const float* bs = (const float*)d_in[6];
    float* out = (float*)d_out;

    prep_w<<<(WPL + 255) / 256, 256>>>(W1);
    dim3 gx((PIX + 31) / 32, CIN / 32, BB);
    prep_x<<<gx, dim3(32, 8)>>>(x);

    cudaFuncSetAttribute(conv_mma, cudaFuncAttributeMaxDynamicSharedMemorySize, CONV_SMEM);
    conv_mma<<<dim3(20, 4, BB), 256, CONV_SMEM>>>(b1);

    heads_part<<<dim3(20, 4, BB), 128>>>(Wl, Ws);
    heads_comb<<<(BB * PIX + 127) / 128, 128>>>(bl, bs, out);

    prep_kernel<<<(BB * NANCH + 255) / 256, 256>>>(out);

    propose_sort<<<BB, 1024>>>();
    propose_mask<<<dim3(10, BB), 128>>>();
    cudaFuncSetAttribute(propose_sweep, cudaFuncAttributeMaxDynamicSharedMemorySize, SWEEP_SMEM);
    propose_sweep<<<BB, 1024, SWEEP_SMEM>>>(out);
}